// round 1
// baseline (speedup 1.0000x reference)
#include <cuda_runtime.h>
#include <math.h>
#include <stdint.h>
#include <stddef.h>

#define MAXN 4

// ---------------- scratch: device globals (no runtime allocation) ----------------
__device__ float g_tmp  [(size_t)MAXN*32*256*256];   // largest raw conv output (L13 deconv)
__device__ float g_buf1 [(size_t)MAXN*32*128*128];
__device__ float g_buf3 [(size_t)MAXN*128*64*64];
__device__ float g_buf5 [(size_t)MAXN*512*32*32];
__device__ float g_buf6 [(size_t)MAXN*256*32*32];
__device__ float g_buf9 [(size_t)MAXN*128*64*64];
__device__ float g_buf12[(size_t)MAXN*64*128*128];
__device__ float g_cat1 [(size_t)MAXN*48*256*256];   // [deconv8 out (32ch) | conv1 out (16ch)]
__device__ float g_cat2 [(size_t)MAXN*128*128*128];  // [deconv6 out (64ch) | caps1b out (64ch)]
__device__ float g_cat3 [(size_t)MAXN*512*64*64];    // [deconv4 out (256ch)| caps2b out (256ch)]

// combined (t0-summed) conv weights, OIHW
__device__ float g_wc1b[64*32*25];
__device__ float g_wc2a[128*64*25];
__device__ float g_wc2b[256*128*25];
__device__ float g_wc3a[512*256*25];
__device__ float g_wc3b[256*512*25];
__device__ float g_wc5 [128*512*25];
__device__ float g_wc7 [64*128*25];
__device__ float g_wc10[16*48*25];
// deconv parity sub-weights: 4 parities, each <= 3x3 taps
__device__ float g_wd4[4][256*256*9];
__device__ float g_wd6[4][64*128*9];
__device__ float g_wd8[4][32*64*9];
__device__ float g_b4s[256];
__device__ float g_b6s[64];
__device__ float g_b8s[32];

// ---------------- weight rearrangement ----------------
// src: [t0][Cout][z0][5][5]  ->  dst: [Cout][t0*z0][5][5]
__global__ void k_rearr_conv(const float* __restrict__ src, float* __restrict__ dst,
                             int t0, int Cout, int z0)
{
    int total = t0 * Cout * z0 * 25;
    int i = blockIdx.x * blockDim.x + threadIdx.x;
    if (i >= total) return;
    int k = i % 25; int r = i / 25;
    int z = r % z0; r /= z0;
    int t = r % t0; int o = r / t0;
    dst[((size_t)(o * t0 + t) * z0 + z) * 25 + k] =
        src[((size_t)(t * Cout + o) * z0 + z) * 25 + k];
}

// src: [t0][z0][Cout][5][5] ; dst: [Cout][t0*z0][KH][KW]  (flipped, parity-subsampled)
__global__ void k_rearr_deconv(const float* __restrict__ src, float* __restrict__ dst,
                               int t0, int z0, int Cout, int ph, int pw, int KH, int KW)
{
    int total = Cout * t0 * z0 * KH * KW;
    int i = blockIdx.x * blockDim.x + threadIdx.x;
    if (i >= total) return;
    int tw = i % KW; int r = i / KW;
    int th = r % KH; r /= KH;
    int z  = r % z0; r /= z0;
    int t  = r % t0; int o = r / t0;
    int kh = 2 * th + ph;
    int kw = 2 * tw + pw;
    dst[(((size_t)(o * t0 + t) * z0 + z) * KH + th) * KW + tw] =
        src[(((size_t)(t * z0 + z) * Cout + o) * 5 + (4 - kh)) * 5 + (4 - kw)];
}

__global__ void k_bias_sum(const float* __restrict__ b, float* __restrict__ o, int t0, int C)
{
    int i = blockIdx.x * blockDim.x + threadIdx.x;
    if (i >= C) return;
    float s = 0.f;
    for (int t = 0; t < t0; ++t) s += b[t * C + i];
    o[i] = s;
}

// ---------------- tiled direct convolution ----------------
// Block tile: 8 (H) x 32 (W) output pixels x 32 output channels.
// Thread: 8 pixels along W x 4 output channels (32 accumulators).
// Input staged per-input-channel into smem; weights staged (broadcast reads).
// Output placement supports channel sub-range (oc0/CoutTot) and strided
// (parity) writes for transposed conv.  Input supports channel sub-range too.
template<int KH, int KW, int S>
__global__ __launch_bounds__(256)
void conv_tiled(const float* __restrict__ x, const float* __restrict__ wgt,
                const float* __restrict__ bias, float* __restrict__ y,
                int Cin, int Hin, int Win, int CinTot, int cin0,
                int Cout, int Hout, int Wout, int padh, int padw,
                int CoutTot, int oc0, int yH, int yW,
                int osH, int osW, int offH, int offW, int nOcTiles)
{
    constexpr int TW = 32, TH = 8, TOC = 32, PIX = 8, OCT = 4;
    constexpr int XW  = (TW - 1) * S + KW;
    constexpr int XH  = (TH - 1) * S + KH;
    constexpr int XWP = (XW & 1) ? XW : XW + 1;   // odd pitch -> fewer bank conflicts
    constexpr int KK  = KH * KW;
    constexpr int SPAN = (PIX - 1) * S + KW;

    __shared__ float sx[XH * XWP];
    __shared__ float sw[TOC * KK];

    const int tid = threadIdx.x;
    const int owg = tid & 3;           // 0..3  (W groups of 8 px)
    const int ohh = (tid >> 2) & 7;    // 0..7  (row within tile)
    const int ocg = tid >> 5;          // 0..7  (oc groups of 4)

    const int wt = blockIdx.x, ht = blockIdx.y;
    const int octile = blockIdx.z % nOcTiles;
    const int n      = blockIdx.z / nOcTiles;

    const int ocb = octile * TOC;
    const int oh0 = ht * TH, ow0 = wt * TW;
    const int ih0 = oh0 * S - padh;
    const int iw0 = ow0 * S - padw;

    float acc[OCT][PIX];
    #pragma unroll
    for (int j = 0; j < OCT; ++j) {
        int oc = ocb + ocg * OCT + j;
        float b = (bias != nullptr && oc < Cout) ? bias[oc] : 0.f;
        #pragma unroll
        for (int i = 0; i < PIX; ++i) acc[j][i] = b;
    }

    const float* xn = x + ((size_t)n * CinTot + cin0) * (size_t)Hin * Win;

    for (int c = 0; c < Cin; ++c) {
        // stage input tile (with zero padding)
        const float* xc = xn + (size_t)c * Hin * Win;
        for (int i = tid; i < XH * XW; i += 256) {
            int rr = i / XW, cc = i % XW;
            int hi = ih0 + rr, wi = iw0 + cc;
            float v = 0.f;
            if (hi >= 0 && hi < Hin && wi >= 0 && wi < Win) v = xc[hi * Win + wi];
            sx[rr * XWP + cc] = v;
        }
        // stage weights for 32 output channels
        for (int i = tid; i < TOC * KK; i += 256) {
            int o = i / KK, k = i % KK;
            float v = 0.f;
            if (ocb + o < Cout) v = wgt[((size_t)(ocb + o) * Cin + c) * KK + k];
            sw[i] = v;
        }
        __syncthreads();

        const int xbase = (ohh * S) * XWP + owg * PIX * S;
        #pragma unroll
        for (int kh = 0; kh < KH; ++kh) {
            float xr[SPAN];
            #pragma unroll
            for (int i = 0; i < SPAN; ++i) xr[i] = sx[xbase + kh * XWP + i];
            #pragma unroll
            for (int kw = 0; kw < KW; ++kw) {
                float wr[OCT];
                #pragma unroll
                for (int j = 0; j < OCT; ++j)
                    wr[j] = sw[(ocg * OCT + j) * KK + kh * KW + kw];
                #pragma unroll
                for (int j = 0; j < OCT; ++j)
                    #pragma unroll
                    for (int i = 0; i < PIX; ++i)
                        acc[j][i] += xr[i * S + kw] * wr[j];
            }
        }
        __syncthreads();
    }

    // store
    const int oh = oh0 + ohh;
    if (oh < Hout) {
        #pragma unroll
        for (int j = 0; j < OCT; ++j) {
            int oc = ocb + ocg * OCT + j;
            if (oc >= Cout) continue;
            float* yo = y + ((size_t)n * CoutTot + oc0 + oc) * (size_t)yH * yW
                          + (size_t)(oh * osH + offH) * yW;
            #pragma unroll
            for (int i = 0; i < PIX; ++i) {
                int ow = ow0 + owg * PIX + i;
                if (ow < Wout) yo[ow * osW + offW] = acc[j][i];
            }
        }
    }
}

// ---------------- routing scale + squash ----------------
// x: raw conv output (N, t1*z1, H, W).  y gets squash(r*x) per z1-group,
// written at channel offset ch0 inside a buffer with CoutTot channels.
__global__ void k_squash(const float* __restrict__ x, float* __restrict__ y,
                         int N, int t1, int z1, int H, int W, int CoutTot, int ch0)
{
    int idx = blockIdx.x * blockDim.x + threadIdx.x;
    int total = N * t1 * H * W;
    if (idx >= total) return;
    int w = idx % W; int t = idx / W;
    int h = t % H;   t /= H;
    int tt = t % t1; int n = t / t1;

    int rlo = h - 2 > 0 ? h - 2 : 0;
    int rhi = h + 2 < H - 1 ? h + 2 : H - 1;
    int clo = w - 2 > 0 ? w - 2 : 0;
    int chi = w + 2 < W - 1 ? w + 2 : W - 1;
    float cnt = (float)((rhi - rlo + 1) * (chi - clo + 1));
    float r = 1.f / ((float)t1 * cnt);

    size_t HW = (size_t)H * W;
    const float* xp = x + ((size_t)(n * t1 + tt) * z1) * HW + (size_t)h * W + w;
    float s2 = 0.f;
    for (int c = 0; c < z1; ++c) { float v = xp[c * HW]; s2 += v * v; }
    float n2 = r * r * s2;
    float f = r * n2 / ((1.f + n2) * sqrtf(n2 + 1e-9f));
    float* yp = y + ((size_t)n * CoutTot + ch0 + tt * z1) * HW + (size_t)h * W + w;
    for (int c = 0; c < z1; ++c) yp[c * HW] = f * xp[c * HW];
}

// final layer: t1=1, z1=16 squash fused with output norm sqrt(sum v^2 + 1e-9)
__global__ void k_final(const float* __restrict__ x, float* __restrict__ out,
                        int N, int H, int W)
{
    int idx = blockIdx.x * blockDim.x + threadIdx.x;
    int total = N * H * W;
    if (idx >= total) return;
    int w = idx % W; int t = idx / W;
    int h = t % H; int n = t / H;

    int rlo = h - 2 > 0 ? h - 2 : 0;
    int rhi = h + 2 < H - 1 ? h + 2 : H - 1;
    int clo = w - 2 > 0 ? w - 2 : 0;
    int chi = w + 2 < W - 1 ? w + 2 : W - 1;
    float cnt = (float)((rhi - rlo + 1) * (chi - clo + 1));
    float r = 1.f / cnt;  // t1 = 1

    size_t HW = (size_t)H * W;
    const float* xp = x + (size_t)n * 16 * HW + (size_t)h * W + w;
    float s2 = 0.f;
    #pragma unroll
    for (int c = 0; c < 16; ++c) { float v = xp[c * HW]; s2 += v * v; }
    float n2 = r * r * s2;
    float f = r * n2 / ((1.f + n2) * sqrtf(n2 + 1e-9f));
    out[(size_t)n * HW + (size_t)h * W + w] = sqrtf(f * f * s2 + 1e-9f);
}

// ---------------- host-side dispatch ----------------
static void run_conv(int KH, int KW, int S,
                     const float* x, const float* w, const float* b, float* y,
                     int N, int Cin, int Hin, int Win, int CinTot, int cin0,
                     int Cout, int Hout, int Wout, int padh, int padw,
                     int CoutTot, int oc0, int yH, int yW,
                     int osH, int osW, int offH, int offW)
{
    int nOcT = (Cout + 31) / 32;
    dim3 grid((Wout + 31) / 32, (Hout + 7) / 8, N * nOcT);
#define CONV_CALL(A,B,C) conv_tiled<A,B,C><<<grid, 256>>>(x, w, b, y, Cin, Hin, Win, CinTot, cin0, \
        Cout, Hout, Wout, padh, padw, CoutTot, oc0, yH, yW, osH, osW, offH, offW, nOcT)
    if      (KH == 5 && KW == 5 && S == 1) CONV_CALL(5,5,1);
    else if (KH == 5 && KW == 5 && S == 2) CONV_CALL(5,5,2);
    else if (KH == 3 && KW == 3)           CONV_CALL(3,3,1);
    else if (KH == 3 && KW == 2)           CONV_CALL(3,2,1);
    else if (KH == 2 && KW == 3)           CONV_CALL(2,3,1);
    else                                   CONV_CALL(2,2,1);
#undef CONV_CALL
}

static float* sym(const void* s)
{
    void* p = nullptr;
    cudaGetSymbolAddress(&p, (const void*)s);
    return (float*)p;
}

extern "C" void kernel_launch(void* const* d_in, const int* in_sizes, int n_in,
                              void* d_out, int out_size)
{
    const float* x    = (const float*)d_in[0];
    const float* w0   = (const float*)d_in[1];   // conv1_w (16,3,5,5)  plain OIHW
    const float* w1a  = (const float*)d_in[2];   // (1,32,16,5,5)  t0=1 -> already OIHW
    const float* w1b  = (const float*)d_in[3];
    const float* w2a  = (const float*)d_in[4];
    const float* w2b  = (const float*)d_in[5];
    const float* w3a  = (const float*)d_in[6];
    const float* w3b  = (const float*)d_in[7];
    const float* w4   = (const float*)d_in[8];
    const float* b4   = (const float*)d_in[9];
    const float* w5   = (const float*)d_in[10];
    const float* w6   = (const float*)d_in[11];
    const float* b6   = (const float*)d_in[12];
    const float* w7   = (const float*)d_in[13];
    const float* w8   = (const float*)d_in[14];
    const float* b8   = (const float*)d_in[15];
    const float* w10  = (const float*)d_in[16];
    float* out = (float*)d_out;
    (void)n_in; (void)out_size;

    const int N = in_sizes[0] / (3 * 256 * 256);

    float* tmp   = sym(&g_tmp);
    float* buf1  = sym(&g_buf1);
    float* buf3  = sym(&g_buf3);
    float* buf5  = sym(&g_buf5);
    float* buf6  = sym(&g_buf6);
    float* buf9  = sym(&g_buf9);
    float* buf12 = sym(&g_buf12);
    float* cat1  = sym(&g_cat1);
    float* cat2  = sym(&g_cat2);
    float* cat3  = sym(&g_cat3);
    float* wc1b  = sym(&g_wc1b);
    float* wc2a  = sym(&g_wc2a);
    float* wc2b  = sym(&g_wc2b);
    float* wc3a  = sym(&g_wc3a);
    float* wc3b  = sym(&g_wc3b);
    float* wc5   = sym(&g_wc5);
    float* wc7   = sym(&g_wc7);
    float* wc10  = sym(&g_wc10);
    float* wd4   = sym(&g_wd4);
    float* wd6   = sym(&g_wd6);
    float* wd8   = sym(&g_wd8);
    float* b4s   = sym(&g_b4s);
    float* b6s   = sym(&g_b6s);
    float* b8s   = sym(&g_b8s);

    // ---- weight prep ----
    auto rc = [](const float* src, float* dst, int t0, int Cout, int z0) {
        int tot = t0 * Cout * z0 * 25;
        k_rearr_conv<<<(tot + 255) / 256, 256>>>(src, dst, t0, Cout, z0);
    };
    rc(w1b, wc1b, 2, 64, 16);
    rc(w2a, wc2a, 4, 128, 16);
    rc(w2b, wc2b, 4, 256, 32);
    rc(w3a, wc3a, 8, 512, 32);
    rc(w3b, wc3b, 8, 256, 64);
    rc(w5,  wc5, 16, 128, 32);
    rc(w7,  wc7,  8, 64, 16);
    rc(w10, wc10, 3, 16, 16);

    auto rd = [](const float* src, float* dstbase, size_t pstride, int t0, int z0, int Cout) {
        for (int ph = 0; ph < 2; ++ph)
            for (int pw = 0; pw < 2; ++pw) {
                int KH = ph ? 2 : 3, KW = pw ? 2 : 3;
                int tot = Cout * t0 * z0 * KH * KW;
                k_rearr_deconv<<<(tot + 255) / 256, 256>>>(
                    src, dstbase + (size_t)(ph * 2 + pw) * pstride, t0, z0, Cout, ph, pw, KH, KW);
            }
    };
    rd(w4, wd4, 256 * 256 * 9, 8, 32, 256);
    rd(w6, wd6, 64 * 128 * 9,  4, 32, 64);
    rd(w8, wd8, 32 * 64 * 9,   4, 16, 32);
    k_bias_sum<<<1, 256>>>(b4, b4s, 8, 256);
    k_bias_sum<<<1, 64>>>(b6, b6s, 4, 64);
    k_bias_sum<<<1, 32>>>(b8, b8s, 4, 32);

    auto squash = [N](const float* src, float* dst, int t1, int z1, int H, int W,
                      int CoutTot, int ch0) {
        int tot = N * t1 * H * W;
        k_squash<<<(tot + 255) / 256, 256>>>(src, dst, N, t1, z1, H, W, CoutTot, ch0);
    };
    auto deconv = [N](const float* in, float* wdbase, size_t pstride, const float* bias,
                      float* y, int Cin, int H, int W, int Cout) {
        for (int ph = 0; ph < 2; ++ph)
            for (int pw = 0; pw < 2; ++pw) {
                int p = ph * 2 + pw;
                run_conv(ph ? 2 : 3, pw ? 2 : 3, 1, in, wdbase + (size_t)p * pstride, bias, y,
                         N, Cin, H, W, Cin, 0, Cout, H, W, ph ? 0 : 1, pw ? 0 : 1,
                         Cout, 0, 2 * H, 2 * W, 2, 2, ph, pw);
            }
    };

    // ---- forward pass ----
    // conv1 -> cat1 channels [32..48)  (this is skip1; stays raw, no squash)
    run_conv(5,5,1, x, w0, nullptr, cat1, N, 3,256,256, 3,0, 16,256,256, 2,2, 48,32, 256,256, 1,1,0,0);
    // caps1a (s=2, t1=2 z1=16)
    run_conv(5,5,2, cat1, w1a, nullptr, tmp, N, 16,256,256, 48,32, 32,128,128, 2,2, 32,0, 128,128, 1,1,0,0);
    squash(tmp, buf1, 2,16,128,128, 32,0);
    // caps1b (t1=4 z1=16) -> cat2 [64..128) (skip2)
    run_conv(5,5,1, buf1, wc1b, nullptr, tmp, N, 32,128,128, 32,0, 64,128,128, 2,2, 64,0, 128,128, 1,1,0,0);
    squash(tmp, cat2, 4,16,128,128, 128,64);
    // caps2a (s=2, t1=4 z1=32)
    run_conv(5,5,2, cat2, wc2a, nullptr, tmp, N, 64,128,128, 128,64, 128,64,64, 2,2, 128,0, 64,64, 1,1,0,0);
    squash(tmp, buf3, 4,32,64,64, 128,0);
    // caps2b (t1=8 z1=32) -> cat3 [256..512) (skip3)
    run_conv(5,5,1, buf3, wc2b, nullptr, tmp, N, 128,64,64, 128,0, 256,64,64, 2,2, 256,0, 64,64, 1,1,0,0);
    squash(tmp, cat3, 8,32,64,64, 512,256);
    // caps3a (s=2, t1=8 z1=64)
    run_conv(5,5,2, cat3, wc3a, nullptr, tmp, N, 256,64,64, 512,256, 512,32,32, 2,2, 512,0, 32,32, 1,1,0,0);
    squash(tmp, buf5, 8,64,32,32, 512,0);
    // caps3b (t1=8 z1=32)
    run_conv(5,5,1, buf5, wc3b, nullptr, tmp, N, 512,32,32, 512,0, 256,32,32, 2,2, 256,0, 32,32, 1,1,0,0);
    squash(tmp, buf6, 8,32,32,32, 256,0);
    // deconv w4 (t1=8 z1=32) -> cat3 [0..256)
    deconv(buf6, wd4, 256*256*9, b4s, tmp, 256, 32, 32, 256);
    squash(tmp, cat3, 8,32,64,64, 512,0);
    // caps w5 on concat (t1=4 z1=32)
    run_conv(5,5,1, cat3, wc5, nullptr, tmp, N, 512,64,64, 512,0, 128,64,64, 2,2, 128,0, 64,64, 1,1,0,0);
    squash(tmp, buf9, 4,32,64,64, 128,0);
    // deconv w6 (t1=4 z1=16) -> cat2 [0..64)
    deconv(buf9, wd6, 64*128*9, b6s, tmp, 128, 64, 64, 64);
    squash(tmp, cat2, 4,16,128,128, 128,0);
    // caps w7 on concat (t1=4 z1=16)
    run_conv(5,5,1, cat2, wc7, nullptr, tmp, N, 128,128,128, 128,0, 64,128,128, 2,2, 64,0, 128,128, 1,1,0,0);
    squash(tmp, buf12, 4,16,128,128, 64,0);
    // deconv w8 (t1=2 z1=16) -> cat1 [0..32)
    deconv(buf12, wd8, 32*64*9, b8s, tmp, 64, 128, 128, 32);
    squash(tmp, cat1, 2,16,256,256, 48,0);
    // caps w10 on concat (t1=1 z1=16) + fused final norm
    run_conv(5,5,1, cat1, wc10, nullptr, tmp, N, 48,256,256, 48,0, 16,256,256, 2,2, 16,0, 256,256, 1,1,0,0);
    k_final<<<(N * 256 * 256 + 255) / 256, 256>>>(tmp, out, N, 256, 256);
}

// round 2
// speedup vs baseline: 1.4819x; 1.4819x over previous
#include <cuda_runtime.h>
#include <math.h>
#include <stdint.h>
#include <stddef.h>

#define MAXN 4

// ---------------- scratch: device globals ----------------
__device__ float g_tmp  [(size_t)MAXN*32*256*256];
__device__ float g_buf1 [(size_t)MAXN*32*128*128];
__device__ float g_buf3 [(size_t)MAXN*128*64*64];
__device__ float g_buf5 [(size_t)MAXN*512*32*32];
__device__ float g_buf6 [(size_t)MAXN*256*32*32];
__device__ float g_buf9 [(size_t)MAXN*128*64*64];
__device__ float g_buf12[(size_t)MAXN*64*128*128];
__device__ float g_cat1 [(size_t)MAXN*48*256*256];
__device__ float g_cat2 [(size_t)MAXN*128*128*128];
__device__ float g_cat3 [(size_t)MAXN*512*64*64];

__device__ float g_wc1b[64*32*25];
__device__ float g_wc2a[128*64*25];
__device__ float g_wc2b[256*128*25];
__device__ float g_wc3a[512*256*25];
__device__ float g_wc3b[256*512*25];
__device__ float g_wc5 [128*512*25];
__device__ float g_wc7 [64*128*25];
__device__ float g_wc10[16*48*25];
__device__ float g_wd4[4][256*256*9];
__device__ float g_wd6[4][64*128*9];
__device__ float g_wd8[4][32*64*9];
__device__ float g_b4s[256];
__device__ float g_b6s[64];
__device__ float g_b8s[32];

// ---------------- packed fp32x2 helpers ----------------
__device__ __forceinline__ unsigned long long pack2(float a, float b)
{
    unsigned long long r;
    asm("mov.b64 %0, {%1, %2};" : "=l"(r) : "r"(__float_as_uint(a)), "r"(__float_as_uint(b)));
    return r;
}
__device__ __forceinline__ void ffma2(unsigned long long& d, unsigned long long a, unsigned long long b)
{
    asm("fma.rn.f32x2 %0, %1, %2, %0;" : "+l"(d) : "l"(a), "l"(b));
}
__device__ __forceinline__ float2 unpack2(unsigned long long v)
{
    unsigned int lo, hi;
    asm("mov.b64 {%0, %1}, %2;" : "=r"(lo), "=r"(hi) : "l"(v));
    float2 f; f.x = __uint_as_float(lo); f.y = __uint_as_float(hi);
    return f;
}

// ---------------- fused weight prep ----------------
struct PrepC {
    const float* src[8]; float* dst[8];
    int t0[8], Cout[8], z0[8];
};
__global__ void k_prep_conv(PrepC a)
{
    int task = blockIdx.y;
    int t0 = a.t0[task], Cout = a.Cout[task], z0 = a.z0[task];
    int total = t0 * Cout * z0 * 25;
    int i = blockIdx.x * 256 + threadIdx.x;
    if (i >= total) return;
    int k = i % 25; int r = i / 25;
    int z = r % z0; r /= z0;
    int t = r % t0; int o = r / t0;
    a.dst[task][((size_t)(o * t0 + t) * z0 + z) * 25 + k] =
        a.src[task][((size_t)(t * Cout + o) * z0 + z) * 25 + k];
}

struct PrepD {
    const float* src[15]; float* dst[15];
    int t0[15], z0[15], Cout[15], ph[15], pw[15], kind[15]; // kind 0=deconv rearr, 1=bias sum
};
__global__ void k_prep_deconv(PrepD a)
{
    int task = blockIdx.y;
    int i = blockIdx.x * 256 + threadIdx.x;
    if (a.kind[task] == 1) {
        int t0 = a.t0[task], C = a.Cout[task];
        if (i >= C) return;
        float s = 0.f;
        for (int t = 0; t < t0; ++t) s += a.src[task][t * C + i];
        a.dst[task][i] = s;
        return;
    }
    int t0 = a.t0[task], z0 = a.z0[task], Cout = a.Cout[task];
    int ph = a.ph[task], pw = a.pw[task];
    int KH = ph ? 2 : 3, KW = pw ? 2 : 3;
    int total = Cout * t0 * z0 * KH * KW;
    if (i >= total) return;
    int tw = i % KW; int r = i / KW;
    int th = r % KH; r /= KH;
    int z  = r % z0; r /= z0;
    int t  = r % t0; int o = r / t0;
    int kh = 2 * th + ph;
    int kw = 2 * tw + pw;
    a.dst[task][(((size_t)(o * t0 + t) * z0 + z) * KH + th) * KW + tw] =
        a.src[task][(((size_t)(t * z0 + z) * Cout + o) * 5 + (4 - kh)) * 5 + (4 - kw)];
}

// ---------------- pipelined tiled direct conv with FFMA2 ----------------
// Block: 8(H) x 32(W) pixels x TOC output channels, 256 threads.
// Thread: 8 pixels x OCT(=TOC/8) channels, accumulated as f32x2 pairs over oc.
// NC input channels staged per sync, double-buffered, register prefetch.
template<int KH, int KW, int S, int TOC, int NC>
__global__ __launch_bounds__(256, 2)
void conv_tiled(const float* __restrict__ x, const float* __restrict__ wgt,
                const float* __restrict__ bias, float* __restrict__ y,
                int Cin, int Hin, int Win, int CinTot, int cin0,
                int Cout, int Hout, int Wout, int padh, int padw,
                int CoutTot, int oc0, int yH, int yW,
                int osH, int osW, int offH, int offW, int nOcTiles)
{
    constexpr int TW = 32, TH = 8, PIX = 8;
    constexpr int OCT = TOC / 8;
    constexpr int NPAIR = OCT / 2;
    constexpr int XW = (TW - 1) * S + KW;
    constexpr int XH = (TH - 1) * S + KH;
    constexpr int XWP = (XW & 1) ? XW : XW + 1;
    constexpr int KK = KH * KW;
    constexpr int SPAN = (PIX - 1) * S + KW;
    constexpr int XTOT = NC * XH * XW;
    constexpr int WTOT = NC * KK * TOC;
    constexpr int XCNT = (XTOT + 255) / 256;
    constexpr int WCNT = (WTOT + 255) / 256;

    __shared__ __align__(16) float sx[2][NC * XH * XWP];
    __shared__ __align__(16) float sw[2][NC * KK * TOC];   // [c][kk][oc]

    const int tid = threadIdx.x;
    const int owg = tid & 3;
    const int ohh = (tid >> 2) & 7;
    const int ocg = tid >> 5;

    const int wt = blockIdx.x, ht = blockIdx.y;
    const int octile = blockIdx.z % nOcTiles;
    const int n      = blockIdx.z / nOcTiles;

    const int ocb = octile * TOC;
    const int oh0 = ht * TH, ow0 = wt * TW;
    const int ih0 = oh0 * S - padh;
    const int iw0 = ow0 * S - padw;
    const size_t HWin = (size_t)Hin * Win;

    unsigned long long acc[NPAIR][PIX];
    #pragma unroll
    for (int p = 0; p < NPAIR; ++p) {
        int oca = ocb + ocg * OCT + 2 * p;
        float b0 = 0.f, b1 = 0.f;
        if (bias != nullptr) {
            if (oca < Cout)     b0 = bias[oca];
            if (oca + 1 < Cout) b1 = bias[oca + 1];
        }
        unsigned long long bi = pack2(b0, b1);
        #pragma unroll
        for (int i = 0; i < PIX; ++i) acc[p][i] = bi;
    }

    const float* xn = x + ((size_t)n * CinTot + cin0) * HWin;
    const int nCh = (Cin + NC - 1) / NC;

    float rx[XCNT], rw[WCNT];

    auto prefetch = [&](int ch) {
        #pragma unroll
        for (int j = 0; j < XCNT; ++j) {
            int g = tid + j * 256; float v = 0.f;
            if (g < XTOT) {
                int c = g / (XH * XW), r = g % (XH * XW);
                int rr = r / XW, cc = r % XW;
                int ci = ch * NC + c;
                int hi = ih0 + rr, wi = iw0 + cc;
                if (ci < Cin && hi >= 0 && hi < Hin && wi >= 0 && wi < Win)
                    v = xn[(size_t)ci * HWin + hi * Win + wi];
            }
            rx[j] = v;
        }
        #pragma unroll
        for (int j = 0; j < WCNT; ++j) {
            int g = tid + j * 256; float v = 0.f;
            if (g < WTOT) {
                int c = g / (KK * TOC), r = g % (KK * TOC);
                int kk = r / TOC, oc = r % TOC;
                int ci = ch * NC + c; int oco = ocb + oc;
                if (ci < Cin && oco < Cout)
                    v = wgt[((size_t)oco * Cin + ci) * KK + kk];
            }
            rw[j] = v;
        }
    };
    auto stage = [&](int buf) {
        #pragma unroll
        for (int j = 0; j < XCNT; ++j) {
            int g = tid + j * 256;
            if (g < XTOT) {
                int c = g / (XH * XW), r = g % (XH * XW);
                int rr = r / XW, cc = r % XW;
                sx[buf][c * (XH * XWP) + rr * XWP + cc] = rx[j];
            }
        }
        #pragma unroll
        for (int j = 0; j < WCNT; ++j) {
            int g = tid + j * 256;
            if (g < WTOT) sw[buf][g] = rw[j];
        }
    };

    prefetch(0);
    stage(0);
    __syncthreads();

    const int xbase = (ohh * S) * XWP + owg * PIX * S;

    for (int ch = 0; ch < nCh; ++ch) {
        const int cur = ch & 1;
        if (ch + 1 < nCh) prefetch(ch + 1);

        const float* sxb = sx[cur];
        const float* swb = sw[cur];
        #pragma unroll 1
        for (int c = 0; c < NC; ++c) {
            const float* sxc = sxb + c * (XH * XWP);
            const float* swc = swb + c * (KK * TOC);
            #pragma unroll
            for (int kh = 0; kh < KH; ++kh) {
                unsigned long long xd[SPAN];
                #pragma unroll
                for (int i = 0; i < SPAN; ++i) {
                    float v = sxc[xbase + kh * XWP + i];
                    xd[i] = pack2(v, v);
                }
                #pragma unroll
                for (int kw = 0; kw < KW; ++kw) {
                    const float* wp = swc + (kh * KW + kw) * TOC + ocg * OCT;
                    #pragma unroll
                    for (int p = 0; p < NPAIR; ++p) {
                        unsigned long long wv = *(const unsigned long long*)(wp + 2 * p);
                        #pragma unroll
                        for (int i = 0; i < PIX; ++i)
                            ffma2(acc[p][i], xd[i * S + kw], wv);
                    }
                }
            }
        }
        if (ch + 1 < nCh) stage((ch + 1) & 1);
        __syncthreads();
    }

    const int oh = oh0 + ohh;
    if (oh < Hout) {
        #pragma unroll
        for (int p = 0; p < NPAIR; ++p) {
            int oca = ocb + ocg * OCT + 2 * p;
            #pragma unroll
            for (int i = 0; i < PIX; ++i) {
                int ow = ow0 + owg * PIX + i;
                if (ow >= Wout) continue;
                float2 v = unpack2(acc[p][i]);
                if (oca < Cout) {
                    float* yo = y + ((size_t)n * CoutTot + oc0 + oca) * (size_t)yH * yW
                                  + (size_t)(oh * osH + offH) * yW;
                    yo[ow * osW + offW] = v.x;
                }
                if (oca + 1 < Cout) {
                    float* yo = y + ((size_t)n * CoutTot + oc0 + oca + 1) * (size_t)yH * yW
                                  + (size_t)(oh * osH + offH) * yW;
                    yo[ow * osW + offW] = v.y;
                }
            }
        }
    }
}

// ---------------- squash / final ----------------
__global__ void k_squash(const float* __restrict__ x, float* __restrict__ y,
                         int N, int t1, int z1, int H, int W, int CoutTot, int ch0)
{
    int idx = blockIdx.x * blockDim.x + threadIdx.x;
    int total = N * t1 * H * W;
    if (idx >= total) return;
    int w = idx % W; int t = idx / W;
    int h = t % H;   t /= H;
    int tt = t % t1; int n = t / t1;

    int rlo = h - 2 > 0 ? h - 2 : 0;
    int rhi = h + 2 < H - 1 ? h + 2 : H - 1;
    int clo = w - 2 > 0 ? w - 2 : 0;
    int chi = w + 2 < W - 1 ? w + 2 : W - 1;
    float cnt = (float)((rhi - rlo + 1) * (chi - clo + 1));
    float r = 1.f / ((float)t1 * cnt);

    size_t HW = (size_t)H * W;
    const float* xp = x + ((size_t)(n * t1 + tt) * z1) * HW + (size_t)h * W + w;
    float s2 = 0.f;
    for (int c = 0; c < z1; ++c) { float v = xp[c * HW]; s2 += v * v; }
    float n2 = r * r * s2;
    float f = r * n2 / ((1.f + n2) * sqrtf(n2 + 1e-9f));
    float* yp = y + ((size_t)n * CoutTot + ch0 + tt * z1) * HW + (size_t)h * W + w;
    for (int c = 0; c < z1; ++c) yp[c * HW] = f * xp[c * HW];
}

__global__ void k_final(const float* __restrict__ x, float* __restrict__ out,
                        int N, int H, int W)
{
    int idx = blockIdx.x * blockDim.x + threadIdx.x;
    int total = N * H * W;
    if (idx >= total) return;
    int w = idx % W; int t = idx / W;
    int h = t % H; int n = t / H;

    int rlo = h - 2 > 0 ? h - 2 : 0;
    int rhi = h + 2 < H - 1 ? h + 2 : H - 1;
    int clo = w - 2 > 0 ? w - 2 : 0;
    int chi = w + 2 < W - 1 ? w + 2 : W - 1;
    float cnt = (float)((rhi - rlo + 1) * (chi - clo + 1));
    float r = 1.f / cnt;

    size_t HW = (size_t)H * W;
    const float* xp = x + (size_t)n * 16 * HW + (size_t)h * W + w;
    float s2 = 0.f;
    #pragma unroll
    for (int c = 0; c < 16; ++c) { float v = xp[c * HW]; s2 += v * v; }
    float n2 = r * r * s2;
    float f = r * n2 / ((1.f + n2) * sqrtf(n2 + 1e-9f));
    out[(size_t)n * HW + (size_t)h * W + w] = sqrtf(f * f * s2 + 1e-9f);
}

// ---------------- host dispatch ----------------
template<int KH, int KW, int S, int TOC>
static void launch_conv(const float* x, const float* w, const float* b, float* y,
                        int N, int Cin, int Hin, int Win, int CinTot, int cin0,
                        int Cout, int Hout, int Wout, int padh, int padw,
                        int CoutTot, int oc0, int yH, int yW,
                        int osH, int osW, int offH, int offW)
{
    constexpr int NC = (S == 2) ? 2 : 4;
    int nOcT = (Cout + TOC - 1) / TOC;
    dim3 grid((Wout + 31) / 32, (Hout + 7) / 8, N * nOcT);
    conv_tiled<KH, KW, S, TOC, NC><<<grid, 256>>>(x, w, b, y, Cin, Hin, Win, CinTot, cin0,
        Cout, Hout, Wout, padh, padw, CoutTot, oc0, yH, yW, osH, osW, offH, offW, nOcT);
}

template<int TOC>
static void run_deconv(const float* in, float* wdbase, size_t pstride, const float* bias,
                       float* y, int N, int Cin, int H, int W, int Cout)
{
    for (int ph = 0; ph < 2; ++ph)
        for (int pw = 0; pw < 2; ++pw) {
            int p = ph * 2 + pw;
            const float* wp = wdbase + (size_t)p * pstride;
#define DCALL(A,B) launch_conv<A,B,1,TOC>(in, wp, bias, y, N, Cin, H, W, Cin, 0, \
                Cout, H, W, ph ? 0 : 1, pw ? 0 : 1, Cout, 0, 2*H, 2*W, 2, 2, ph, pw)
            if      (ph == 0 && pw == 0) DCALL(3,3);
            else if (ph == 0 && pw == 1) DCALL(3,2);
            else if (ph == 1 && pw == 0) DCALL(2,3);
            else                         DCALL(2,2);
#undef DCALL
        }
}

static float* sym(const void* s)
{
    void* p = nullptr;
    cudaGetSymbolAddress(&p, (const void*)s);
    return (float*)p;
}

extern "C" void kernel_launch(void* const* d_in, const int* in_sizes, int n_in,
                              void* d_out, int out_size)
{
    const float* x    = (const float*)d_in[0];
    const float* w0   = (const float*)d_in[1];
    const float* w1a  = (const float*)d_in[2];
    const float* w1b  = (const float*)d_in[3];
    const float* w2a  = (const float*)d_in[4];
    const float* w2b  = (const float*)d_in[5];
    const float* w3a  = (const float*)d_in[6];
    const float* w3b  = (const float*)d_in[7];
    const float* w4   = (const float*)d_in[8];
    const float* b4   = (const float*)d_in[9];
    const float* w5   = (const float*)d_in[10];
    const float* w6   = (const float*)d_in[11];
    const float* b6   = (const float*)d_in[12];
    const float* w7   = (const float*)d_in[13];
    const float* w8   = (const float*)d_in[14];
    const float* b8   = (const float*)d_in[15];
    const float* w10  = (const float*)d_in[16];
    float* out = (float*)d_out;
    (void)n_in; (void)out_size;

    const int N = in_sizes[0] / (3 * 256 * 256);

    float* tmp   = sym(&g_tmp);
    float* buf1  = sym(&g_buf1);
    float* buf3  = sym(&g_buf3);
    float* buf5  = sym(&g_buf5);
    float* buf6  = sym(&g_buf6);
    float* buf9  = sym(&g_buf9);
    float* buf12 = sym(&g_buf12);
    float* cat1  = sym(&g_cat1);
    float* cat2  = sym(&g_cat2);
    float* cat3  = sym(&g_cat3);
    float* wc1b  = sym(&g_wc1b);
    float* wc2a  = sym(&g_wc2a);
    float* wc2b  = sym(&g_wc2b);
    float* wc3a  = sym(&g_wc3a);
    float* wc3b  = sym(&g_wc3b);
    float* wc5   = sym(&g_wc5);
    float* wc7   = sym(&g_wc7);
    float* wc10  = sym(&g_wc10);
    float* wd4   = sym(&g_wd4);
    float* wd6   = sym(&g_wd6);
    float* wd8   = sym(&g_wd8);
    float* b4s   = sym(&g_b4s);
    float* b6s   = sym(&g_b6s);
    float* b8s   = sym(&g_b8s);

    // ---- weight prep: 2 fused launches ----
    {
        PrepC pc;
        const float* srcs[8] = {w1b, w2a, w2b, w3a, w3b, w5, w7, w10};
        float*       dsts[8] = {wc1b, wc2a, wc2b, wc3a, wc3b, wc5, wc7, wc10};
        int t0s[8]   = {2, 4, 4, 8, 8, 16, 8, 3};
        int couts[8] = {64, 128, 256, 512, 256, 128, 64, 16};
        int z0s[8]   = {16, 16, 32, 32, 64, 32, 16, 16};
        int maxTot = 0;
        for (int i = 0; i < 8; ++i) {
            pc.src[i] = srcs[i]; pc.dst[i] = dsts[i];
            pc.t0[i] = t0s[i]; pc.Cout[i] = couts[i]; pc.z0[i] = z0s[i];
            int tot = t0s[i] * couts[i] * z0s[i] * 25;
            if (tot > maxTot) maxTot = tot;
        }
        dim3 g((maxTot + 255) / 256, 8);
        k_prep_conv<<<g, 256>>>(pc);
    }
    {
        PrepD pd;
        const float* dsrc[3]  = {w4, w6, w8};
        float*       dbase[3] = {wd4, wd6, wd8};
        size_t pstr[3] = {256 * 256 * 9, 64 * 128 * 9, 32 * 64 * 9};
        int dt0[3] = {8, 4, 4}, dz0[3] = {32, 32, 16}, dco[3] = {256, 64, 32};
        int idx = 0, maxTot = 0;
        for (int d = 0; d < 3; ++d)
            for (int ph = 0; ph < 2; ++ph)
                for (int pw = 0; pw < 2; ++pw) {
                    pd.src[idx] = dsrc[d];
                    pd.dst[idx] = dbase[d] + (size_t)(ph * 2 + pw) * pstr[d];
                    pd.t0[idx] = dt0[d]; pd.z0[idx] = dz0[d]; pd.Cout[idx] = dco[d];
                    pd.ph[idx] = ph; pd.pw[idx] = pw; pd.kind[idx] = 0;
                    int KH = ph ? 2 : 3, KW = pw ? 2 : 3;
                    int tot = dco[d] * dt0[d] * dz0[d] * KH * KW;
                    if (tot > maxTot) maxTot = tot;
                    ++idx;
                }
        const float* bsrc[3] = {b4, b6, b8};
        float*       bdst[3] = {b4s, b6s, b8s};
        int bt0[3] = {8, 4, 4}, bC[3] = {256, 64, 32};
        for (int d = 0; d < 3; ++d) {
            pd.src[idx] = bsrc[d]; pd.dst[idx] = bdst[d];
            pd.t0[idx] = bt0[d]; pd.Cout[idx] = bC[d];
            pd.z0[idx] = 0; pd.ph[idx] = 0; pd.pw[idx] = 0; pd.kind[idx] = 1;
            ++idx;
        }
        dim3 g((maxTot + 255) / 256, 15);
        k_prep_deconv<<<g, 256>>>(pd);
    }

    auto squash = [N](const float* src, float* dst, int t1, int z1, int H, int W,
                      int CoutTot, int ch0) {
        int tot = N * t1 * H * W;
        k_squash<<<(tot + 255) / 256, 256>>>(src, dst, N, t1, z1, H, W, CoutTot, ch0);
    };

    // ---- forward pass ----
    // conv1 -> cat1 channels [32..48)  (skip1, raw)
    launch_conv<5,5,1,32>(x, w0, nullptr, cat1, N, 3,256,256, 3,0, 16,256,256, 2,2, 48,32, 256,256, 1,1,0,0);
    // caps1a (s=2, t1=2 z1=16)
    launch_conv<5,5,2,32>(cat1, w1a, nullptr, tmp, N, 16,256,256, 48,32, 32,128,128, 2,2, 32,0, 128,128, 1,1,0,0);
    squash(tmp, buf1, 2,16,128,128, 32,0);
    // caps1b (t1=4 z1=16) -> cat2 [64..128) (skip2)   [profiled launch #6]
    launch_conv<5,5,1,32>(buf1, wc1b, nullptr, tmp, N, 32,128,128, 32,0, 64,128,128, 2,2, 64,0, 128,128, 1,1,0,0);
    squash(tmp, cat2, 4,16,128,128, 128,64);
    // caps2a (s=2, t1=4 z1=32)
    launch_conv<5,5,2,32>(cat2, wc2a, nullptr, tmp, N, 64,128,128, 128,64, 128,64,64, 2,2, 128,0, 64,64, 1,1,0,0);
    squash(tmp, buf3, 4,32,64,64, 128,0);
    // caps2b (t1=8 z1=32) -> cat3 [256..512) (skip3)
    launch_conv<5,5,1,32>(buf3, wc2b, nullptr, tmp, N, 128,64,64, 128,0, 256,64,64, 2,2, 256,0, 64,64, 1,1,0,0);
    squash(tmp, cat3, 8,32,64,64, 512,256);
    // caps3a (s=2, t1=8 z1=64)  [32x32 out -> TOC=16]
    launch_conv<5,5,2,16>(cat3, wc3a, nullptr, tmp, N, 256,64,64, 512,256, 512,32,32, 2,2, 512,0, 32,32, 1,1,0,0);
    squash(tmp, buf5, 8,64,32,32, 512,0);
    // caps3b (t1=8 z1=32)  [32x32 -> TOC=16]
    launch_conv<5,5,1,16>(buf5, wc3b, nullptr, tmp, N, 512,32,32, 512,0, 256,32,32, 2,2, 256,0, 32,32, 1,1,0,0);
    squash(tmp, buf6, 8,32,32,32, 256,0);
    // deconv w4 (t1=8 z1=32) -> cat3 [0..256)   [TOC=16]
    run_deconv<16>(buf6, wd4, 256*256*9, b4s, tmp, N, 256, 32, 32, 256);
    squash(tmp, cat3, 8,32,64,64, 512,0);
    // caps w5 (t1=4 z1=32)
    launch_conv<5,5,1,32>(cat3, wc5, nullptr, tmp, N, 512,64,64, 512,0, 128,64,64, 2,2, 128,0, 64,64, 1,1,0,0);
    squash(tmp, buf9, 4,32,64,64, 128,0);
    // deconv w6 (t1=4 z1=16) -> cat2 [0..64)   [TOC=16]
    run_deconv<16>(buf9, wd6, 64*128*9, b6s, tmp, N, 128, 64, 64, 64);
    squash(tmp, cat2, 4,16,128,128, 128,0);
    // caps w7 (t1=4 z1=16)
    launch_conv<5,5,1,32>(cat2, wc7, nullptr, tmp, N, 128,128,128, 128,0, 64,128,128, 2,2, 64,0, 128,128, 1,1,0,0);
    squash(tmp, buf12, 4,16,128,128, 64,0);
    // deconv w8 (t1=2 z1=16) -> cat1 [0..32)   [TOC=32]
    run_deconv<32>(buf12, wd8, 32*64*9, b8s, tmp, N, 64, 128, 128, 32);
    squash(tmp, cat1, 2,16,256,256, 48,0);
    // caps w10 (t1=1 z1=16) + fused final norm   [Cout=16 -> TOC=16]
    launch_conv<5,5,1,16>(cat1, wc10, nullptr, tmp, N, 48,256,256, 48,0, 16,256,256, 2,2, 16,0, 256,256, 1,1,0,0);
    k_final<<<(N * 256 * 256 + 255) / 256, 256>>>(tmp, out, N, 256, 256);
}

// round 4
// speedup vs baseline: 1.4965x; 1.0099x over previous
#include <cuda_runtime.h>
#include <math.h>
#include <stdint.h>
#include <stddef.h>

#define MAXN 4

// ---------------- scratch: device globals ----------------
__device__ float g_tmp  [(size_t)MAXN*32*256*256];
__device__ float g_buf1 [(size_t)MAXN*32*128*128];
__device__ float g_buf3 [(size_t)MAXN*128*64*64];
__device__ float g_buf5 [(size_t)MAXN*512*32*32];
__device__ float g_buf6 [(size_t)MAXN*256*32*32];
__device__ float g_buf9 [(size_t)MAXN*128*64*64];
__device__ float g_buf12[(size_t)MAXN*64*128*128];
__device__ float g_cat1 [(size_t)MAXN*48*256*256];
__device__ float g_cat2 [(size_t)MAXN*128*128*128];
__device__ float g_cat3 [(size_t)MAXN*512*64*64];

__device__ float g_wc1b[64*32*25];
__device__ float g_wc2a[128*64*25];
__device__ float g_wc2b[256*128*25];
__device__ float g_wc3a[512*256*25];
__device__ float g_wc3b[256*512*25];
__device__ float g_wc5 [128*512*25];
__device__ float g_wc7 [64*128*25];
__device__ float g_wc10[16*48*25];
// fused deconv weights: [Cin][25 taps][Cout]
__device__ float g_wdf4[256*25*256];
__device__ float g_wdf6[128*25*64];
__device__ float g_wdf8[64*25*32];
__device__ float g_b4s[256];
__device__ float g_b6s[64];
__device__ float g_b8s[32];

// ---------------- packed fp32x2 helpers ----------------
__device__ __forceinline__ unsigned long long pack2(float a, float b)
{
    unsigned long long r;
    asm("mov.b64 %0, {%1, %2};" : "=l"(r) : "r"(__float_as_uint(a)), "r"(__float_as_uint(b)));
    return r;
}
__device__ __forceinline__ void ffma2(unsigned long long& d, unsigned long long a, unsigned long long b)
{
    asm("fma.rn.f32x2 %0, %1, %2, %0;" : "+l"(d) : "l"(a), "l"(b));
}
__device__ __forceinline__ float2 unpack2(unsigned long long v)
{
    unsigned int lo, hi;
    asm("mov.b64 {%0, %1}, %2;" : "=r"(lo), "=r"(hi) : "l"(v));
    float2 f; f.x = __uint_as_float(lo); f.y = __uint_as_float(hi);
    return f;
}

__device__ __forceinline__ float route_f(int oh, int ow, int H, int W, float t1, float s2)
{
    int rlo = oh - 2 > 0 ? oh - 2 : 0;
    int rhi = oh + 2 < H - 1 ? oh + 2 : H - 1;
    int clo = ow - 2 > 0 ? ow - 2 : 0;
    int chi = ow + 2 < W - 1 ? ow + 2 : W - 1;
    float cnt = (float)((rhi - rlo + 1) * (chi - clo + 1));
    float r = 1.f / (t1 * cnt);
    float n2 = r * r * s2;
    return r * n2 / ((1.f + n2) * sqrtf(n2 + 1e-9f));
}

// ---------------- fused weight prep ----------------
struct PrepC {
    const float* src[8]; float* dst[8];
    int t0[8], Cout[8], z0[8];
};
__global__ void k_prep_conv(PrepC a)
{
    int task = blockIdx.y;
    int t0 = a.t0[task], Cout = a.Cout[task], z0 = a.z0[task];
    int total = t0 * Cout * z0 * 25;
    int i = blockIdx.x * 256 + threadIdx.x;
    if (i >= total) return;
    int k = i % 25; int r = i / 25;
    int z = r % z0; r /= z0;
    int t = r % t0; int o = r / t0;
    a.dst[task][((size_t)(o * t0 + t) * z0 + z) * 25 + k] =
        a.src[task][((size_t)(t * Cout + o) * z0 + z) * 25 + k];
}

// deconv: src [t0][z0][Cout][5][5] -> dst [Cin=t0*z0][25 taps][Cout]
// tap order: 0..8 parity(0,0) (dh+1)*3+(dw+1) ; 9..14 p(0,1) (dh+1)*2+dw ;
//            15..20 p(1,0) dh*3+(dw+1) ; 21..24 p(1,1) dh*2+dw
struct PrepD {
    const float* src[6]; float* dst[6];
    int Cin[6], Cout[6], t0[6], kind[6];  // kind 0 = rearrange, 1 = bias sum
};
__global__ void k_prep_dec(PrepD a)
{
    int task = blockIdx.y;
    int i = blockIdx.x * 256 + threadIdx.x;
    int Cout = a.Cout[task];
    if (a.kind[task] == 1) {
        if (i >= Cout) return;
        float s = 0.f;
        for (int t = 0; t < a.t0[task]; ++t) s += a.src[task][t * Cout + i];
        a.dst[task][i] = s;
        return;
    }
    int Cin = a.Cin[task];
    int total = Cin * 25 * Cout;
    if (i >= total) return;
    int o = i % Cout; int r = i / Cout;
    int tap = r % 25; int c = r / 25;
    int ph, pw, dh, dw;
    if (tap < 9)       { ph = 0; pw = 0; dh = tap / 3 - 1;       dw = tap % 3 - 1; }
    else if (tap < 15) { int t = tap - 9;  ph = 0; pw = 1; dh = t / 2 - 1; dw = t % 2; }
    else if (tap < 21) { int t = tap - 15; ph = 1; pw = 0; dh = t / 3;     dw = t % 3 - 1; }
    else               { int t = tap - 21; ph = 1; pw = 1; dh = t / 2;     dw = t % 2; }
    int kh = 2 * (dh + (ph ? 0 : 1)) + ph;
    int kw = 2 * (dw + (pw ? 0 : 1)) + pw;
    a.dst[task][i] = a.src[task][((size_t)c * Cout + o) * 25 + (4 - kh) * 5 + (4 - kw)];
}

// ---------------- pipelined tiled conv, optional fused squash ----------------
template<int KH, int KW, int S, int TOC, int NC, int Z1, bool FINAL>
__global__ __launch_bounds__(256, 2)
void conv_tiled(const float* __restrict__ x, const float* __restrict__ wgt,
                const float* __restrict__ bias, float* __restrict__ y,
                int Cin, int Hin, int Win, int CinTot, int cin0,
                int Cout, int Hout, int Wout, int padh, int padw,
                int CoutTot, int oc0, int t1i, int nOcTiles)
{
    constexpr int TW = 32, TH = 8, PIX = 8;
    constexpr int OCT = TOC / 8;
    constexpr int NPAIR = OCT / 2;
    constexpr int XW = (TW - 1) * S + KW;
    constexpr int XH = (TH - 1) * S + KH;
    constexpr int XWP = (XW & 1) ? XW : XW + 1;
    constexpr int KK = KH * KW;
    constexpr int SPAN = (PIX - 1) * S + KW;
    constexpr int XTOT = NC * XH * XW;
    constexpr int WTOT = NC * KK * TOC;
    constexpr int XCNT = (XTOT + 255) / 256;
    constexpr int WCNT = (WTOT + 255) / 256;
    constexpr int SXSZ = 2 * NC * XH * XWP;
    static_assert(Z1 == 0 || (Z1 % OCT == 0 && TOC % Z1 == 0), "z1 grouping");
    static_assert(Z1 == 0 || SXSZ >= 2048, "ps overlay fits");

    __shared__ __align__(16) float smem_all[SXSZ + 2 * WTOT];
    float* sxA = smem_all;
    float* swA = smem_all + SXSZ;

    const int tid = threadIdx.x;
    const int owg = tid & 3;
    const int ohh = (tid >> 2) & 7;
    const int ocg = tid >> 5;
    const int lane = tid & 31;

    const int wt = blockIdx.x, ht = blockIdx.y;
    const int octile = blockIdx.z % nOcTiles;
    const int n      = blockIdx.z / nOcTiles;

    const int ocb = octile * TOC;
    const int oh0 = ht * TH, ow0 = wt * TW;
    const int ih0 = oh0 * S - padh;
    const int iw0 = ow0 * S - padw;
    const size_t HWin = (size_t)Hin * Win;

    unsigned long long acc[NPAIR][PIX];
    #pragma unroll
    for (int p = 0; p < NPAIR; ++p) {
        int oca = ocb + ocg * OCT + 2 * p;
        float b0 = 0.f, b1 = 0.f;
        if (bias != nullptr) {
            if (oca < Cout)     b0 = bias[oca];
            if (oca + 1 < Cout) b1 = bias[oca + 1];
        }
        unsigned long long bi = pack2(b0, b1);
        #pragma unroll
        for (int i = 0; i < PIX; ++i) acc[p][i] = bi;
    }

    const float* xn = x + ((size_t)n * CinTot + cin0) * HWin;
    const int nCh = (Cin + NC - 1) / NC;

    float rx[XCNT], rw[WCNT];

    auto prefetch = [&](int ch) {
        #pragma unroll
        for (int j = 0; j < XCNT; ++j) {
            int g = tid + j * 256; float v = 0.f;
            if (g < XTOT) {
                int c = g / (XH * XW), r = g % (XH * XW);
                int rr = r / XW, cc = r % XW;
                int ci = ch * NC + c;
                int hi = ih0 + rr, wi = iw0 + cc;
                if (ci < Cin && hi >= 0 && hi < Hin && wi >= 0 && wi < Win)
                    v = xn[(size_t)ci * HWin + hi * Win + wi];
            }
            rx[j] = v;
        }
        #pragma unroll
        for (int j = 0; j < WCNT; ++j) {
            int g = tid + j * 256; float v = 0.f;
            if (g < WTOT) {
                int c = g / (KK * TOC), r = g % (KK * TOC);
                int kk = r / TOC, oc = r % TOC;
                int ci = ch * NC + c; int oco = ocb + oc;
                if (ci < Cin && oco < Cout)
                    v = wgt[((size_t)oco * Cin + ci) * KK + kk];
            }
            rw[j] = v;
        }
    };
    auto stage = [&](int buf) {
        #pragma unroll
        for (int j = 0; j < XCNT; ++j) {
            int g = tid + j * 256;
            if (g < XTOT) {
                int c = g / (XH * XW), r = g % (XH * XW);
                int rr = r / XW, cc = r % XW;
                sxA[buf * (NC * XH * XWP) + c * (XH * XWP) + rr * XWP + cc] = rx[j];
            }
        }
        #pragma unroll
        for (int j = 0; j < WCNT; ++j) {
            int g = tid + j * 256;
            if (g < WTOT) swA[buf * WTOT + g] = rw[j];
        }
    };

    prefetch(0);
    stage(0);
    __syncthreads();

    const int xbase = (ohh * S) * XWP + owg * PIX * S;

    for (int ch = 0; ch < nCh; ++ch) {
        const int cur = ch & 1;
        if (ch + 1 < nCh) prefetch(ch + 1);

        const float* sxb = sxA + cur * (NC * XH * XWP);
        const float* swb = swA + cur * WTOT;
        #pragma unroll 1
        for (int c = 0; c < NC; ++c) {
            const float* sxc = sxb + c * (XH * XWP);
            const float* swc = swb + c * (KK * TOC);
            #pragma unroll
            for (int kh = 0; kh < KH; ++kh) {
                unsigned long long xd[SPAN];
                #pragma unroll
                for (int i = 0; i < SPAN; ++i) {
                    float v = sxc[xbase + kh * XWP + i];
                    xd[i] = pack2(v, v);
                }
                #pragma unroll
                for (int kw = 0; kw < KW; ++kw) {
                    const float* wp = swc + (kh * KW + kw) * TOC + ocg * OCT;
                    #pragma unroll
                    for (int p = 0; p < NPAIR; ++p) {
                        unsigned long long wv = *(const unsigned long long*)(wp + 2 * p);
                        #pragma unroll
                        for (int i = 0; i < PIX; ++i)
                            ffma2(acc[p][i], xd[i * S + kw], wv);
                    }
                }
            }
        }
        if (ch + 1 < nCh) stage((ch + 1) & 1);
        __syncthreads();
    }

    const int oh = oh0 + ohh;

    if (Z1 == 0) {
        if (oh < Hout) {
            #pragma unroll
            for (int p = 0; p < NPAIR; ++p) {
                int oca = ocb + ocg * OCT + 2 * p;
                #pragma unroll
                for (int i = 0; i < PIX; ++i) {
                    int ow = ow0 + owg * PIX + i;
                    if (ow >= Wout) continue;
                    float2 v = unpack2(acc[p][i]);
                    if (oca < Cout)
                        y[(((size_t)n * CoutTot + oc0 + oca) * Hout + oh) * Wout + ow] = v.x;
                    if (oca + 1 < Cout)
                        y[(((size_t)n * CoutTot + oc0 + oca + 1) * Hout + oh) * Wout + ow] = v.y;
                }
            }
        }
    } else {
        // fused squash: cross-warp z1-group reduce via smem overlay
        float* ps = smem_all;
        #pragma unroll
        for (int i = 0; i < PIX; ++i) {
            float s = 0.f;
            #pragma unroll
            for (int p = 0; p < NPAIR; ++p) {
                float2 v = unpack2(acc[p][i]);
                s += v.x * v.x + v.y * v.y;
            }
            ps[ocg * 256 + i * 32 + lane] = s;
        }
        __syncthreads();
        constexpr int GPERZ = (Z1 > 0) ? Z1 / OCT : 1;
        const int g0 = (ocg / GPERZ) * GPERZ;
        const float t1f = (float)t1i;
        #pragma unroll
        for (int i = 0; i < PIX; ++i) {
            int ow = ow0 + owg * PIX + i;
            float s2 = 0.f;
            #pragma unroll
            for (int g = 0; g < GPERZ; ++g) s2 += ps[(g0 + g) * 256 + i * 32 + lane];
            float f = route_f(oh, ow, Hout, Wout, t1f, s2);
            if (oh >= Hout || ow >= Wout) continue;
            if (FINAL) {
                if (ocg == 0)
                    y[((size_t)n * Hout + oh) * Wout + ow] = sqrtf(f * f * s2 + 1e-9f);
            } else {
                #pragma unroll
                for (int p = 0; p < NPAIR; ++p) {
                    int oca = ocb + ocg * OCT + 2 * p;
                    float2 v = unpack2(acc[p][i]);
                    y[(((size_t)n * CoutTot + oc0 + oca) * Hout + oh) * Wout + ow] = f * v.x;
                    y[(((size_t)n * CoutTot + oc0 + oca + 1) * Hout + oh) * Wout + ow] = f * v.y;
                }
            }
        }
    }
}

// ---------------- fused 4-parity deconv (lhs_dilation=2), optional squash ----------------
// Input H x W, output 2H x 2W.  TOC=16 (OCT=2, one acc pair per parity).
template<int TOC, int Z1, int NC>
__global__ __launch_bounds__(256, 2)
void deconv_tiled(const float* __restrict__ x, const float* __restrict__ wgt,
                  const float* __restrict__ bias, float* __restrict__ y,
                  int Cin, int H, int W, int Cout, int CoutTot, int t1i, int nOcTiles)
{
    constexpr int TW = 32, TH = 8, PIX = 8;
    constexpr int OCT = TOC / 8;
    static_assert(OCT == 2, "deconv uses OCT=2");
    constexpr int XW = TW + 2, XH = TH + 2, XWP = XW + 1;  // 34 -> pitch 35
    constexpr int XTOT = NC * XH * XW;
    constexpr int WTOT = NC * 25 * TOC;
    constexpr int XCNT = (XTOT + 255) / 256;
    constexpr int WCNT = (WTOT + 255) / 256;
    constexpr int SXSZ = 2 * NC * XH * XWP;
    constexpr int SMSZ = (SXSZ + 2 * WTOT) > 2048 ? (SXSZ + 2 * WTOT) : 2048;

    __shared__ __align__(16) float smem_all[SMSZ];
    float* sxA = smem_all;
    float* swA = smem_all + SXSZ;

    const int tid = threadIdx.x;
    const int owg = tid & 3;
    const int ohh = (tid >> 2) & 7;
    const int ocg = tid >> 5;
    const int lane = tid & 31;

    const int wt = blockIdx.x, ht = blockIdx.y;
    const int octile = blockIdx.z % nOcTiles;
    const int n      = blockIdx.z / nOcTiles;

    const int ocb = octile * TOC;
    const int oh0 = ht * TH, ow0 = wt * TW;
    const int ih0 = oh0 - 1, iw0 = ow0 - 1;
    const size_t HWin = (size_t)H * W;
    const int yH = 2 * H, yW = 2 * W;

    const int oca = ocb + ocg * OCT;
    unsigned long long bi = pack2(bias[oca], bias[oca + 1]);
    unsigned long long acc[4][PIX];
    #pragma unroll
    for (int par = 0; par < 4; ++par)
        #pragma unroll
        for (int i = 0; i < PIX; ++i) acc[par][i] = bi;

    const float* xn = x + (size_t)n * Cin * HWin;
    const int nCh = (Cin + NC - 1) / NC;

    float rx[XCNT], rw[WCNT];
    auto prefetch = [&](int ch) {
        #pragma unroll
        for (int j = 0; j < XCNT; ++j) {
            int g = tid + j * 256; float v = 0.f;
            if (g < XTOT) {
                int c = g / (XH * XW), r = g % (XH * XW);
                int rr = r / XW, cc = r % XW;
                int ci = ch * NC + c;
                int hi = ih0 + rr, wi = iw0 + cc;
                if (ci < Cin && hi >= 0 && hi < H && wi >= 0 && wi < W)
                    v = xn[(size_t)ci * HWin + hi * W + wi];
            }
            rx[j] = v;
        }
        #pragma unroll
        for (int j = 0; j < WCNT; ++j) {
            int g = tid + j * 256; float v = 0.f;
            if (g < WTOT) {
                int c = g / (25 * TOC), r = g % (25 * TOC);
                int tap = r / TOC, oc = r % TOC;
                int ci = ch * NC + c;
                if (ci < Cin)
                    v = wgt[((size_t)ci * 25 + tap) * Cout + ocb + oc];
            }
            rw[j] = v;
        }
    };
    auto stage = [&](int buf) {
        #pragma unroll
        for (int j = 0; j < XCNT; ++j) {
            int g = tid + j * 256;
            if (g < XTOT) {
                int c = g / (XH * XW), r = g % (XH * XW);
                int rr = r / XW, cc = r % XW;
                sxA[buf * (NC * XH * XWP) + c * (XH * XWP) + rr * XWP + cc] = rx[j];
            }
        }
        #pragma unroll
        for (int j = 0; j < WCNT; ++j) {
            int g = tid + j * 256;
            if (g < WTOT) swA[buf * WTOT + g] = rw[j];
        }
    };

    prefetch(0);
    stage(0);
    __syncthreads();

    for (int ch = 0; ch < nCh; ++ch) {
        const int cur = ch & 1;
        if (ch + 1 < nCh) prefetch(ch + 1);

        const float* sxb = sxA + cur * (NC * XH * XWP);
        const float* swb = swA + cur * WTOT;
        #pragma unroll 1
        for (int c = 0; c < NC; ++c) {
            const float* sxc = sxb + c * (XH * XWP);
            const float* swc = swb + c * (25 * TOC);
            #pragma unroll
            for (int dh = -1; dh <= 1; ++dh) {
                unsigned long long xd[10];
                const int rbase = (ohh + 1 + dh) * XWP + owg * PIX;
                #pragma unroll
                for (int j = 0; j < 10; ++j) {
                    float v = sxc[rbase + j];
                    xd[j] = pack2(v, v);
                }
                // parity (0,0): taps 0..8
                #pragma unroll
                for (int dw = -1; dw <= 1; ++dw) {
                    unsigned long long wv = *(const unsigned long long*)
                        (swc + ((dh + 1) * 3 + (dw + 1)) * TOC + ocg * OCT);
                    #pragma unroll
                    for (int i = 0; i < PIX; ++i) ffma2(acc[0][i], xd[i + dw + 1], wv);
                }
                // parity (0,1): taps 9..14
                #pragma unroll
                for (int dw = 0; dw <= 1; ++dw) {
                    unsigned long long wv = *(const unsigned long long*)
                        (swc + (9 + (dh + 1) * 2 + dw) * TOC + ocg * OCT);
                    #pragma unroll
                    for (int i = 0; i < PIX; ++i) ffma2(acc[1][i], xd[i + dw + 1], wv);
                }
                if (dh >= 0) {
                    // parity (1,0): taps 15..20
                    #pragma unroll
                    for (int dw = -1; dw <= 1; ++dw) {
                        unsigned long long wv = *(const unsigned long long*)
                            (swc + (15 + dh * 3 + (dw + 1)) * TOC + ocg * OCT);
                        #pragma unroll
                        for (int i = 0; i < PIX; ++i) ffma2(acc[2][i], xd[i + dw + 1], wv);
                    }
                    // parity (1,1): taps 21..24
                    #pragma unroll
                    for (int dw = 0; dw <= 1; ++dw) {
                        unsigned long long wv = *(const unsigned long long*)
                            (swc + (21 + dh * 2 + dw) * TOC + ocg * OCT);
                        #pragma unroll
                        for (int i = 0; i < PIX; ++i) ffma2(acc[3][i], xd[i + dw + 1], wv);
                    }
                }
            }
        }
        if (ch + 1 < nCh) stage((ch + 1) & 1);
        __syncthreads();
    }

    // store (H,W multiples of 8/32 and Cout multiple of TOC: no guards)
    if (Z1 == 0) {
        #pragma unroll
        for (int par = 0; par < 4; ++par) {
            const int ph = par >> 1, pw = par & 1;
            const int oh = 2 * (oh0 + ohh) + ph;
            #pragma unroll
            for (int i = 0; i < PIX; ++i) {
                int ow = 2 * (ow0 + owg * PIX + i) + pw;
                float2 v = unpack2(acc[par][i]);
                y[(((size_t)n * CoutTot + oca) * yH + oh) * yW + ow] = v.x;
                y[(((size_t)n * CoutTot + oca + 1) * yH + oh) * yW + ow] = v.y;
            }
        }
    } else {
        static_assert(Z1 == 0 || Z1 == TOC, "deconv squash: one group per tile");
        float* ps = smem_all;
        const float t1f = (float)t1i;
        #pragma unroll 1
        for (int par = 0; par < 4; ++par) {
            const int ph = par >> 1, pw = par & 1;
            const int oh = 2 * (oh0 + ohh) + ph;
            #pragma unroll
            for (int i = 0; i < PIX; ++i) {
                float2 v = unpack2(acc[par][i]);
                ps[ocg * 256 + i * 32 + lane] = v.x * v.x + v.y * v.y;
            }
            __syncthreads();
            #pragma unroll
            for (int i = 0; i < PIX; ++i) {
                int ow = 2 * (ow0 + owg * PIX + i) + pw;
                float s2 = 0.f;
                #pragma unroll
                for (int g = 0; g < 8; ++g) s2 += ps[g * 256 + i * 32 + lane];
                float f = route_f(oh, ow, yH, yW, t1f, s2);
                float2 v = unpack2(acc[par][i]);
                y[(((size_t)n * CoutTot + oca) * yH + oh) * yW + ow] = f * v.x;
                y[(((size_t)n * CoutTot + oca + 1) * yH + oh) * yW + ow] = f * v.y;
            }
            __syncthreads();
        }
    }
}

// ---------------- standalone squash (z1 > tile) ----------------
__global__ void k_squash(const float* __restrict__ x, float* __restrict__ y,
                         int N, int t1, int z1, int H, int W, int CoutTot, int ch0)
{
    int idx = blockIdx.x * blockDim.x + threadIdx.x;
    int total = N * t1 * H * W;
    if (idx >= total) return;
    int w = idx % W; int t = idx / W;
    int h = t % H;   t /= H;
    int tt = t % t1; int n = t / t1;

    size_t HW = (size_t)H * W;
    const float* xp = x + ((size_t)(n * t1 + tt) * z1) * HW + (size_t)h * W + w;
    float s2 = 0.f;
    for (int c = 0; c < z1; ++c) { float v = xp[c * HW]; s2 += v * v; }
    float f = route_f(h, w, H, W, (float)t1, s2);
    float* yp = y + ((size_t)n * CoutTot + ch0 + tt * z1) * HW + (size_t)h * W + w;
    for (int c = 0; c < z1; ++c) yp[c * HW] = f * xp[c * HW];
}

// ---------------- host dispatch ----------------
template<int KH, int KW, int S, int TOC, int Z1, bool FINAL>
static void launch_conv(const float* x, const float* w, const float* b, float* y,
                        int N, int Cin, int Hin, int Win, int CinTot, int cin0,
                        int Cout, int Hout, int Wout, int padh, int padw,
                        int CoutTot, int oc0, int t1)
{
    constexpr int NC = (S == 2) ? 2 : 4;
    int nOcT = (Cout + TOC - 1) / TOC;
    dim3 grid((Wout + 31) / 32, (Hout + 7) / 8, N * nOcT);
    conv_tiled<KH, KW, S, TOC, NC, Z1, FINAL><<<grid, 256>>>(
        x, w, b, y, Cin, Hin, Win, CinTot, cin0,
        Cout, Hout, Wout, padh, padw, CoutTot, oc0, t1, nOcT);
}

template<int Z1>
static void launch_deconv(const float* x, const float* w, const float* b, float* y,
                          int N, int Cin, int H, int W, int Cout, int CoutTot, int t1)
{
    constexpr int TOC = 16;
    int nOcT = Cout / TOC;
    dim3 grid(W / 32, H / 8, N * nOcT);
    deconv_tiled<TOC, Z1, 2><<<grid, 256>>>(x, w, b, y, Cin, H, W, Cout, CoutTot, t1, nOcT);
}

static float* sym(const void* s)
{
    void* p = nullptr;
    cudaGetSymbolAddress(&p, (const void*)s);
    return (float*)p;
}

extern "C" void kernel_launch(void* const* d_in, const int* in_sizes, int n_in,
                              void* d_out, int out_size)
{
    const float* x    = (const float*)d_in[0];
    const float* w0   = (const float*)d_in[1];
    const float* w1a  = (const float*)d_in[2];
    const float* w1b  = (const float*)d_in[3];
    const float* w2a  = (const float*)d_in[4];
    const float* w2b  = (const float*)d_in[5];
    const float* w3a  = (const float*)d_in[6];
    const float* w3b  = (const float*)d_in[7];
    const float* w4   = (const float*)d_in[8];
    const float* b4   = (const float*)d_in[9];
    const float* w5   = (const float*)d_in[10];
    const float* w6   = (const float*)d_in[11];
    const float* b6   = (const float*)d_in[12];
    const float* w7   = (const float*)d_in[13];
    const float* w8   = (const float*)d_in[14];
    const float* b8   = (const float*)d_in[15];
    const float* w10  = (const float*)d_in[16];
    float* out = (float*)d_out;
    (void)n_in; (void)out_size;

    const int N = in_sizes[0] / (3 * 256 * 256);

    float* tmp   = sym(&g_tmp);
    float* buf1  = sym(&g_buf1);
    float* buf3  = sym(&g_buf3);
    float* buf5  = sym(&g_buf5);
    float* buf6  = sym(&g_buf6);
    float* buf9  = sym(&g_buf9);
    float* buf12 = sym(&g_buf12);
    float* cat1  = sym(&g_cat1);
    float* cat2  = sym(&g_cat2);
    float* cat3  = sym(&g_cat3);
    float* wc1b  = sym(&g_wc1b);
    float* wc2a  = sym(&g_wc2a);
    float* wc2b  = sym(&g_wc2b);
    float* wc3a  = sym(&g_wc3a);
    float* wc3b  = sym(&g_wc3b);
    float* wc5   = sym(&g_wc5);
    float* wc7   = sym(&g_wc7);
    float* wc10  = sym(&g_wc10);
    float* wdf4  = sym(&g_wdf4);
    float* wdf6  = sym(&g_wdf6);
    float* wdf8  = sym(&g_wdf8);
    float* b4s   = sym(&g_b4s);
    float* b6s   = sym(&g_b6s);
    float* b8s   = sym(&g_b8s);

    // ---- weight prep: 2 fused launches ----
    {
        PrepC pc;
        const float* srcs[8] = {w1b, w2a, w2b, w3a, w3b, w5, w7, w10};
        float*       dsts[8] = {wc1b, wc2a, wc2b, wc3a, wc3b, wc5, wc7, wc10};
        int t0s[8]   = {2, 4, 4, 8, 8, 16, 8, 3};
        int couts[8] = {64, 128, 256, 512, 256, 128, 64, 16};
        int z0s[8]   = {16, 16, 32, 32, 64, 32, 16, 16};
        int maxTot = 0;
        for (int i = 0; i < 8; ++i) {
            pc.src[i] = srcs[i]; pc.dst[i] = dsts[i];
            pc.t0[i] = t0s[i]; pc.Cout[i] = couts[i]; pc.z0[i] = z0s[i];
            int tot = t0s[i] * couts[i] * z0s[i] * 25;
            if (tot > maxTot) maxTot = tot;
        }
        dim3 g((maxTot + 255) / 256, 8);
        k_prep_conv<<<g, 256>>>(pc);
    }
    {
        PrepD pd;
        const float* wsrc[3] = {w4, w6, w8};
        float*       wdst[3] = {wdf4, wdf6, wdf8};
        int cins[3]  = {256, 128, 64};
        int couts[3] = {256, 64, 32};
        int t0s[3]   = {8, 4, 4};
        const float* bsrc[3] = {b4, b6, b8};
        float*       bdst[3] = {b4s, b6s, b8s};
        int maxTot = 0;
        for (int d = 0; d < 3; ++d) {
            pd.src[d] = wsrc[d]; pd.dst[d] = wdst[d];
            pd.Cin[d] = cins[d]; pd.Cout[d] = couts[d]; pd.t0[d] = t0s[d]; pd.kind[d] = 0;
            int tot = cins[d] * 25 * couts[d];
            if (tot > maxTot) maxTot = tot;
            pd.src[3 + d] = bsrc[d]; pd.dst[3 + d] = bdst[d];
            pd.Cin[3 + d] = 0; pd.Cout[3 + d] = couts[d]; pd.t0[3 + d] = t0s[d]; pd.kind[3 + d] = 1;
        }
        dim3 g((maxTot + 255) / 256, 6);
        k_prep_dec<<<g, 256>>>(pd);
    }

    // ---- forward pass ----
    // conv1 -> cat1 [32..48)  (skip1, raw, no squash)
    launch_conv<5,5,1,16,0,false>(x, w0, nullptr, cat1, N, 3,256,256, 3,0, 16,256,256, 2,2, 48,32, 0);
    // caps1a (s=2, t1=2 z1=16) fused squash -> buf1
    launch_conv<5,5,2,32,16,false>(cat1, w1a, nullptr, buf1, N, 16,256,256, 48,32, 32,128,128, 2,2, 32,0, 2);
    // caps1b (t1=4 z1=16) fused -> cat2 [64..128) (skip2)
    launch_conv<5,5,1,32,16,false>(buf1, wc1b, nullptr, cat2, N, 32,128,128, 32,0, 64,128,128, 2,2, 128,64, 4);
    // caps2a (s=2, t1=4 z1=32) fused -> buf3          [profiled launch #6]
    launch_conv<5,5,2,32,32,false>(cat2, wc2a, nullptr, buf3, N, 64,128,128, 128,64, 128,64,64, 2,2, 128,0, 4);
    // caps2b (t1=8 z1=32) fused -> cat3 [256..512) (skip3)
    launch_conv<5,5,1,32,32,false>(buf3, wc2b, nullptr, cat3, N, 128,64,64, 128,0, 256,64,64, 2,2, 512,256, 8);
    // caps3a (s=2, t1=8 z1=64): z1 > tile -> unfused
    launch_conv<5,5,2,16,0,false>(cat3, wc3a, nullptr, tmp, N, 256,64,64, 512,256, 512,32,32, 2,2, 512,0, 0);
    k_squash<<<(N*8*32*32 + 255)/256, 256>>>(tmp, buf5, N, 8,64,32,32, 512,0);
    // caps3b (t1=8 z1=32): TOC=16 < z1 -> unfused
    launch_conv<5,5,1,16,0,false>(buf5, wc3b, nullptr, tmp, N, 512,32,32, 512,0, 256,32,32, 2,2, 256,0, 0);
    k_squash<<<(N*8*32*32 + 255)/256, 256>>>(tmp, buf6, N, 8,32,32,32, 256,0);
    // deconv w4 (t1=8 z1=32): fused 4-parity, squash separate (z1 > tile)
    launch_deconv<0>(buf6, wdf4, b4s, tmp, N, 256, 32, 32, 256, 256, 0);
    k_squash<<<(N*8*64*64 + 255)/256, 256>>>(tmp, cat3, N, 8,32,64,64, 512,0);
    // caps w5 (t1=4 z1=32) fused -> buf9
    launch_conv<5,5,1,32,32,false>(cat3, wc5, nullptr, buf9, N, 512,64,64, 512,0, 128,64,64, 2,2, 128,0, 4);
    // deconv w6 (t1=4 z1=16): fused parity + squash -> cat2 [0..64)
    launch_deconv<16>(buf9, wdf6, b6s, cat2, N, 128, 64, 64, 64, 128, 4);
    // caps w7 (t1=4 z1=16) fused -> buf12
    launch_conv<5,5,1,32,16,false>(cat2, wc7, nullptr, buf12, N, 128,128,128, 128,0, 64,128,128, 2,2, 64,0, 4);
    // deconv w8 (t1=2 z1=16): fused parity + squash -> cat1 [0..32)
    launch_deconv<16>(buf12, wdf8, b8s, cat1, N, 64, 128, 128, 32, 48, 2);
    // caps w10 (t1=1 z1=16) fused squash + final norm -> out
    launch_conv<5,5,1,16,16,true>(cat1, wc10, nullptr, out, N, 48,256,256, 48,0, 16,256,256, 2,2, 1,0, 1);
}

// round 5
// speedup vs baseline: 1.7192x; 1.1488x over previous
#include <cuda_runtime.h>
#include <math.h>
#include <stdint.h>
#include <stddef.h>

#define MAXN 4

// ---------------- scratch: device globals ----------------
__device__ float g_tmp  [(size_t)MAXN*32*256*256];
__device__ float g_buf1 [(size_t)MAXN*32*128*128];
__device__ float g_buf3 [(size_t)MAXN*128*64*64];
__device__ float g_buf5 [(size_t)MAXN*512*32*32];
__device__ float g_buf6 [(size_t)MAXN*256*32*32];
__device__ float g_buf9 [(size_t)MAXN*128*64*64];
__device__ float g_buf12[(size_t)MAXN*64*128*128];
__device__ float g_cat1 [(size_t)MAXN*48*256*256];
__device__ float g_cat2 [(size_t)MAXN*128*128*128];
__device__ float g_cat3 [(size_t)MAXN*512*64*64];

// conv weights, layout [cin][25][Cout]
__device__ float g_wc0 [3*25*16];
__device__ float g_wc1a[16*25*32];
__device__ float g_wc1b[32*25*64];
__device__ float g_wc2a[64*25*128];
__device__ float g_wc2b[128*25*256];
__device__ float g_wc3a[256*25*512];
__device__ float g_wc3b[512*25*256];
__device__ float g_wc5 [512*25*128];
__device__ float g_wc7 [128*25*64];
__device__ float g_wc10[48*25*16];
// fused deconv weights: [Cin][25 taps][Cout]
__device__ float g_wdf4[256*25*256];
__device__ float g_wdf6[128*25*64];
__device__ float g_wdf8[64*25*32];
__device__ float g_b4s[256];
__device__ float g_b6s[64];
__device__ float g_b8s[32];

// ---------------- helpers ----------------
__device__ __forceinline__ unsigned long long pack2(float a, float b)
{
    unsigned long long r;
    asm("mov.b64 %0, {%1, %2};" : "=l"(r) : "r"(__float_as_uint(a)), "r"(__float_as_uint(b)));
    return r;
}
__device__ __forceinline__ void ffma2(unsigned long long& d, unsigned long long a, unsigned long long b)
{
    asm("fma.rn.f32x2 %0, %1, %2, %0;" : "+l"(d) : "l"(a), "l"(b));
}
__device__ __forceinline__ float2 unpack2(unsigned long long v)
{
    unsigned int lo, hi;
    asm("mov.b64 {%0, %1}, %2;" : "=r"(lo), "=r"(hi) : "l"(v));
    float2 f; f.x = __uint_as_float(lo); f.y = __uint_as_float(hi);
    return f;
}
__device__ __forceinline__ uint32_t saddr(const void* p)
{
    return (uint32_t)__cvta_generic_to_shared(p);
}
__device__ __forceinline__ void cpa4(uint32_t dst, const float* src, bool ok)
{
    int sz = ok ? 4 : 0;
    asm volatile("cp.async.ca.shared.global [%0], [%1], 4, %2;" :: "r"(dst), "l"(src), "r"(sz) : "memory");
}
__device__ __forceinline__ void cpa16(uint32_t dst, const float* src, bool ok)
{
    int sz = ok ? 16 : 0;
    asm volatile("cp.async.cg.shared.global [%0], [%1], 16, %2;" :: "r"(dst), "l"(src), "r"(sz) : "memory");
}
#define CP_COMMIT() asm volatile("cp.async.commit_group;" ::: "memory")
#define CP_WAIT0()  asm volatile("cp.async.wait_group 0;" ::: "memory")

__device__ __forceinline__ float route_f(int oh, int ow, int H, int W, float t1, float s2)
{
    int rlo = oh - 2 > 0 ? oh - 2 : 0;
    int rhi = oh + 2 < H - 1 ? oh + 2 : H - 1;
    int clo = ow - 2 > 0 ? ow - 2 : 0;
    int chi = ow + 2 < W - 1 ? ow + 2 : W - 1;
    float cnt = (float)((rhi - rlo + 1) * (chi - clo + 1));
    float r = 1.f / (t1 * cnt);
    float n2 = r * r * s2;
    return r * n2 / ((1.f + n2) * sqrtf(n2 + 1e-9f));
}

// ---------------- fused weight prep ----------------
// conv: src [t0][Cout][z0][5][5] -> dst [cin=t0*z0][25][Cout]
struct PrepC {
    const float* src[10]; float* dst[10];
    int t0[10], Cout[10], z0[10];
};
__global__ void k_prep_conv(PrepC a)
{
    int task = blockIdx.y;
    int t0 = a.t0[task], Cout = a.Cout[task], z0 = a.z0[task];
    int total = t0 * z0 * 25 * Cout;
    int i = blockIdx.x * 256 + threadIdx.x;
    if (i >= total) return;
    int o = i % Cout; int r = i / Cout;
    int k = r % 25; r /= 25;
    int z = r % z0; int t = r / z0;
    a.dst[task][i] = a.src[task][((size_t)(t * Cout + o) * z0 + z) * 25 + k];
}

// deconv: src [t0][z0][Cout][5][5] -> dst [Cin][25 taps][Cout]
struct PrepD {
    const float* src[6]; float* dst[6];
    int Cin[6], Cout[6], t0[6], kind[6];
};
__global__ void k_prep_dec(PrepD a)
{
    int task = blockIdx.y;
    int i = blockIdx.x * 256 + threadIdx.x;
    int Cout = a.Cout[task];
    if (a.kind[task] == 1) {
        if (i >= Cout) return;
        float s = 0.f;
        for (int t = 0; t < a.t0[task]; ++t) s += a.src[task][t * Cout + i];
        a.dst[task][i] = s;
        return;
    }
    int Cin = a.Cin[task];
    int total = Cin * 25 * Cout;
    if (i >= total) return;
    int o = i % Cout; int r = i / Cout;
    int tap = r % 25; int c = r / 25;
    int ph, pw, dh, dw;
    if (tap < 9)       { ph = 0; pw = 0; dh = tap / 3 - 1;       dw = tap % 3 - 1; }
    else if (tap < 15) { int t = tap - 9;  ph = 0; pw = 1; dh = t / 2 - 1; dw = t % 2; }
    else if (tap < 21) { int t = tap - 15; ph = 1; pw = 0; dh = t / 3;     dw = t % 3 - 1; }
    else               { int t = tap - 21; ph = 1; pw = 1; dh = t / 2;     dw = t % 2; }
    int kh = 2 * (dh + (ph ? 0 : 1)) + ph;
    int kw = 2 * (dw + (pw ? 0 : 1)) + pw;
    a.dst[task][i] = a.src[task][((size_t)c * Cout + o) * 25 + (4 - kh) * 5 + (4 - kw)];
}

// ---------------- cp.async pipelined tiled conv, optional fused squash ----------------
template<int KH, int KW, int S, int TOC, int NC, int Z1, bool FINAL>
__global__ __launch_bounds__(256, 3)
void conv_tiled(const float* __restrict__ x, const float* __restrict__ wgt,
                float* __restrict__ y,
                int Cin, int Hin, int Win, int CinTot, int cin0,
                int Cout, int Hout, int Wout, int padh, int padw,
                int CoutTot, int oc0, int t1i, int nOcTiles)
{
    constexpr int TW = 32, TH = 8, PIX = 8;
    constexpr int OCT = TOC / 8;
    constexpr int NPAIR = OCT / 2;
    constexpr int XW = (TW - 1) * S + KW;
    constexpr int XH = (TH - 1) * S + KH;
    constexpr int XWP = (XW & 1) ? XW : XW + 1;
    constexpr int KK = KH * KW;
    constexpr int SPAN = (PIX - 1) * S + KW;
    constexpr int XTOT = NC * XH * XW;
    constexpr int WTOT = NC * KK * TOC;
    constexpr int XCNT = (XTOT + 255) / 256;
    constexpr int WQ   = WTOT / 4;
    constexpr int WQCNT = (WQ + 255) / 256;
    constexpr int SXSZ = 2 * NC * XH * XWP;
    static_assert(Z1 == 0 || (Z1 % OCT == 0 && TOC % Z1 == 0), "z1 grouping");
    static_assert(Z1 == 0 || SXSZ + 2 * WTOT >= 2048, "ps overlay fits");

    __shared__ __align__(16) float smem_all[SXSZ + 2 * WTOT];

    const int tid = threadIdx.x;
    const int owg = tid & 3;
    const int ohh = (tid >> 2) & 7;
    const int ocg = tid >> 5;
    const int lane = tid & 31;

    const int wt = blockIdx.x, ht = blockIdx.y;
    const int octile = blockIdx.z % nOcTiles;
    const int n      = blockIdx.z / nOcTiles;

    const int ocb = octile * TOC;
    const int oh0 = ht * TH, ow0 = wt * TW;
    const int ih0 = oh0 * S - padh;
    const int iw0 = ow0 * S - padw;
    const size_t HWin = (size_t)Hin * Win;

    const float* xn = x + ((size_t)n * CinTot + cin0) * HWin;
    const float* wb = wgt + ocb;
    const int nCh = (Cin + NC - 1) / NC;

    const uint32_t sxa = saddr(smem_all);
    const uint32_t swa = sxa + SXSZ * 4;

    unsigned long long acc[NPAIR][PIX];
    #pragma unroll
    for (int p = 0; p < NPAIR; ++p)
        #pragma unroll
        for (int i = 0; i < PIX; ++i) acc[p][i] = 0ull;

    auto issue = [&](int ch, int buf) {
        #pragma unroll
        for (int j = 0; j < XCNT; ++j) {
            int g = tid + j * 256;
            if (g < XTOT) {
                int c = g / (XH * XW), r = g % (XH * XW);
                int rr = r / XW, cc = r % XW;
                int ci = ch * NC + c;
                int hi = ih0 + rr, wi = iw0 + cc;
                bool ok = (ci < Cin) && (hi >= 0) && (hi < Hin) && (wi >= 0) && (wi < Win);
                const float* src = ok ? xn + (size_t)ci * HWin + (size_t)hi * Win + wi : xn;
                cpa4(sxa + (uint32_t)(buf * (NC * XH * XWP) + c * (XH * XWP) + rr * XWP + cc) * 4,
                     src, ok);
            }
        }
        #pragma unroll
        for (int j = 0; j < WQCNT; ++j) {
            int q = tid + j * 256;
            if (q < WQ) {
                int idx = q * 4;
                int c = idx / (KK * TOC), r = idx % (KK * TOC);
                int kk = r / TOC, oc = r % TOC;
                int ci = ch * NC + c;
                bool ok = ci < Cin;
                const float* src = ok ? wb + ((size_t)ci * KK + kk) * Cout + oc : wgt;
                cpa16(swa + (uint32_t)(buf * WTOT + idx) * 4, src, ok);
            }
        }
        CP_COMMIT();
    };

    issue(0, 0);

    const int xbase = (ohh * S) * XWP + owg * PIX * S;

    for (int ch = 0; ch < nCh; ++ch) {
        CP_WAIT0();
        __syncthreads();
        if (ch + 1 < nCh) issue(ch + 1, (ch + 1) & 1);

        const float* sxb = smem_all + (ch & 1) * (NC * XH * XWP);
        const float* swb = smem_all + SXSZ + (ch & 1) * WTOT;
        #pragma unroll 1
        for (int c = 0; c < NC; ++c) {
            const float* sxc = sxb + c * (XH * XWP);
            const float* swc = swb + c * (KK * TOC);
            #pragma unroll
            for (int kh = 0; kh < KH; ++kh) {
                float xr[SPAN];
                #pragma unroll
                for (int i = 0; i < SPAN; ++i) xr[i] = sxc[xbase + kh * XWP + i];
                #pragma unroll
                for (int kw = 0; kw < KW; ++kw) {
                    const float* wp = swc + (kh * KW + kw) * TOC + ocg * OCT;
                    #pragma unroll
                    for (int p = 0; p < NPAIR; ++p) {
                        unsigned long long wv = *(const unsigned long long*)(wp + 2 * p);
                        #pragma unroll
                        for (int i = 0; i < PIX; ++i)
                            ffma2(acc[p][i], pack2(xr[i * S + kw], xr[i * S + kw]), wv);
                    }
                }
            }
        }
    }

    const int oh = oh0 + ohh;

    if (Z1 == 0) {
        #pragma unroll
        for (int p = 0; p < NPAIR; ++p) {
            int oca = ocb + ocg * OCT + 2 * p;
            float* y0 = y + (((size_t)n * CoutTot + oc0 + oca) * Hout + oh) * Wout;
            float* y1 = y0 + (size_t)Hout * Wout;
            #pragma unroll
            for (int i = 0; i < PIX; ++i) {
                int ow = ow0 + owg * PIX + i;
                float2 v = unpack2(acc[p][i]);
                y0[ow] = v.x;
                y1[ow] = v.y;
            }
        }
    } else {
        __syncthreads();   // protect smem overlay against threads still reading tiles
        float* ps = smem_all;
        #pragma unroll
        for (int i = 0; i < PIX; ++i) {
            float s = 0.f;
            #pragma unroll
            for (int p = 0; p < NPAIR; ++p) {
                float2 v = unpack2(acc[p][i]);
                s += v.x * v.x + v.y * v.y;
            }
            ps[ocg * 256 + i * 32 + lane] = s;
        }
        __syncthreads();
        constexpr int GPERZ = (Z1 > 0) ? Z1 / OCT : 1;
        const int g0 = (ocg / GPERZ) * GPERZ;
        const float t1f = (float)t1i;
        #pragma unroll
        for (int i = 0; i < PIX; ++i) {
            int ow = ow0 + owg * PIX + i;
            float s2 = 0.f;
            #pragma unroll
            for (int g = 0; g < GPERZ; ++g) s2 += ps[(g0 + g) * 256 + i * 32 + lane];
            float f = route_f(oh, ow, Hout, Wout, t1f, s2);
            if (FINAL) {
                if (ocg == 0)
                    y[((size_t)n * Hout + oh) * Wout + ow] = sqrtf(f * f * s2 + 1e-9f);
            } else {
                #pragma unroll
                for (int p = 0; p < NPAIR; ++p) {
                    int oca = ocb + ocg * OCT + 2 * p;
                    float2 v = unpack2(acc[p][i]);
                    y[(((size_t)n * CoutTot + oc0 + oca) * Hout + oh) * Wout + ow] = f * v.x;
                    y[(((size_t)n * CoutTot + oc0 + oca + 1) * Hout + oh) * Wout + ow] = f * v.y;
                }
            }
        }
    }
}

// ---------------- fused 4-parity deconv with cp.async, optional squash ----------------
template<int TOC, int Z1, int NC>
__global__ __launch_bounds__(256, 2)
void deconv_tiled(const float* __restrict__ x, const float* __restrict__ wgt,
                  const float* __restrict__ bias, float* __restrict__ y,
                  int Cin, int H, int W, int Cout, int CoutTot, int t1i, int nOcTiles)
{
    constexpr int TW = 32, TH = 8, PIX = 8;
    constexpr int OCT = TOC / 8;
    static_assert(OCT == 2, "deconv uses OCT=2");
    constexpr int XW = TW + 2, XH = TH + 2, XWP = XW + 1;
    constexpr int XTOT = NC * XH * XW;
    constexpr int WTOT = NC * 25 * TOC;
    constexpr int XCNT = (XTOT + 255) / 256;
    constexpr int WQ   = WTOT / 4;
    constexpr int WQCNT = (WQ + 255) / 256;
    constexpr int SXSZ = 2 * NC * XH * XWP;
    constexpr int SMSZ = (SXSZ + 2 * WTOT) > 2048 ? (SXSZ + 2 * WTOT) : 2048;

    __shared__ __align__(16) float smem_all[SMSZ];

    const int tid = threadIdx.x;
    const int owg = tid & 3;
    const int ohh = (tid >> 2) & 7;
    const int ocg = tid >> 5;
    const int lane = tid & 31;

    const int wt = blockIdx.x, ht = blockIdx.y;
    const int octile = blockIdx.z % nOcTiles;
    const int n      = blockIdx.z / nOcTiles;

    const int ocb = octile * TOC;
    const int oh0 = ht * TH, ow0 = wt * TW;
    const int ih0 = oh0 - 1, iw0 = ow0 - 1;
    const size_t HWin = (size_t)H * W;
    const int yH = 2 * H, yW = 2 * W;

    const int oca = ocb + ocg * OCT;
    unsigned long long bi = pack2(bias[oca], bias[oca + 1]);
    unsigned long long acc[4][PIX];
    #pragma unroll
    for (int par = 0; par < 4; ++par)
        #pragma unroll
        for (int i = 0; i < PIX; ++i) acc[par][i] = bi;

    const float* xn = x + (size_t)n * Cin * HWin;
    const float* wb = wgt + ocb;
    const int nCh = (Cin + NC - 1) / NC;

    const uint32_t sxa = saddr(smem_all);
    const uint32_t swa = sxa + SXSZ * 4;

    auto issue = [&](int ch, int buf) {
        #pragma unroll
        for (int j = 0; j < XCNT; ++j) {
            int g = tid + j * 256;
            if (g < XTOT) {
                int c = g / (XH * XW), r = g % (XH * XW);
                int rr = r / XW, cc = r % XW;
                int ci = ch * NC + c;
                int hi = ih0 + rr, wi = iw0 + cc;
                bool ok = (ci < Cin) && (hi >= 0) && (hi < H) && (wi >= 0) && (wi < W);
                const float* src = ok ? xn + (size_t)ci * HWin + (size_t)hi * W + wi : xn;
                cpa4(sxa + (uint32_t)(buf * (NC * XH * XWP) + c * (XH * XWP) + rr * XWP + cc) * 4,
                     src, ok);
            }
        }
        #pragma unroll
        for (int j = 0; j < WQCNT; ++j) {
            int q = tid + j * 256;
            if (q < WQ) {
                int idx = q * 4;
                int c = idx / (25 * TOC), r = idx % (25 * TOC);
                int tap = r / TOC, oc = r % TOC;
                int ci = ch * NC + c;
                bool ok = ci < Cin;
                const float* src = ok ? wb + ((size_t)ci * 25 + tap) * Cout + oc : wgt;
                cpa16(swa + (uint32_t)(buf * WTOT + idx) * 4, src, ok);
            }
        }
        CP_COMMIT();
    };

    issue(0, 0);

    for (int ch = 0; ch < nCh; ++ch) {
        CP_WAIT0();
        __syncthreads();
        if (ch + 1 < nCh) issue(ch + 1, (ch + 1) & 1);

        const float* sxb = smem_all + (ch & 1) * (NC * XH * XWP);
        const float* swb = smem_all + SXSZ + (ch & 1) * WTOT;
        #pragma unroll 1
        for (int c = 0; c < NC; ++c) {
            const float* sxc = sxb + c * (XH * XWP);
            const float* swc = swb + c * (25 * TOC);
            #pragma unroll
            for (int dh = -1; dh <= 1; ++dh) {
                float xr[10];
                const int rbase = (ohh + 1 + dh) * XWP + owg * PIX;
                #pragma unroll
                for (int j = 0; j < 10; ++j) xr[j] = sxc[rbase + j];
                #pragma unroll
                for (int dw = -1; dw <= 1; ++dw) {
                    unsigned long long wv = *(const unsigned long long*)
                        (swc + ((dh + 1) * 3 + (dw + 1)) * TOC + ocg * OCT);
                    #pragma unroll
                    for (int i = 0; i < PIX; ++i)
                        ffma2(acc[0][i], pack2(xr[i + dw + 1], xr[i + dw + 1]), wv);
                }
                #pragma unroll
                for (int dw = 0; dw <= 1; ++dw) {
                    unsigned long long wv = *(const unsigned long long*)
                        (swc + (9 + (dh + 1) * 2 + dw) * TOC + ocg * OCT);
                    #pragma unroll
                    for (int i = 0; i < PIX; ++i)
                        ffma2(acc[1][i], pack2(xr[i + dw + 1], xr[i + dw + 1]), wv);
                }
                if (dh >= 0) {
                    #pragma unroll
                    for (int dw = -1; dw <= 1; ++dw) {
                        unsigned long long wv = *(const unsigned long long*)
                            (swc + (15 + dh * 3 + (dw + 1)) * TOC + ocg * OCT);
                        #pragma unroll
                        for (int i = 0; i < PIX; ++i)
                            ffma2(acc[2][i], pack2(xr[i + dw + 1], xr[i + dw + 1]), wv);
                    }
                    #pragma unroll
                    for (int dw = 0; dw <= 1; ++dw) {
                        unsigned long long wv = *(const unsigned long long*)
                            (swc + (21 + dh * 2 + dw) * TOC + ocg * OCT);
                        #pragma unroll
                        for (int i = 0; i < PIX; ++i)
                            ffma2(acc[3][i], pack2(xr[i + dw + 1], xr[i + dw + 1]), wv);
                    }
                }
            }
        }
    }

    if (Z1 == 0) {
        #pragma unroll
        for (int par = 0; par < 4; ++par) {
            const int ph = par >> 1, pw = par & 1;
            const int oh = 2 * (oh0 + ohh) + ph;
            float* y0 = y + (((size_t)n * CoutTot + oca) * yH + oh) * yW;
            float* y1 = y0 + (size_t)yH * yW;
            #pragma unroll
            for (int i = 0; i < PIX; ++i) {
                int ow = 2 * (ow0 + owg * PIX + i) + pw;
                float2 v = unpack2(acc[par][i]);
                y0[ow] = v.x;
                y1[ow] = v.y;
            }
        }
    } else {
        static_assert(Z1 == 0 || Z1 == TOC, "deconv squash: one group per tile");
        __syncthreads();
        float* ps = smem_all;
        const float t1f = (float)t1i;
        #pragma unroll 1
        for (int par = 0; par < 4; ++par) {
            const int ph = par >> 1, pw = par & 1;
            const int oh = 2 * (oh0 + ohh) + ph;
            #pragma unroll
            for (int i = 0; i < PIX; ++i) {
                float2 v = unpack2(acc[par][i]);
                ps[ocg * 256 + i * 32 + lane] = v.x * v.x + v.y * v.y;
            }
            __syncthreads();
            #pragma unroll
            for (int i = 0; i < PIX; ++i) {
                int ow = 2 * (ow0 + owg * PIX + i) + pw;
                float s2 = 0.f;
                #pragma unroll
                for (int g = 0; g < 8; ++g) s2 += ps[g * 256 + i * 32 + lane];
                float f = route_f(oh, ow, yH, yW, t1f, s2);
                float2 v = unpack2(acc[par][i]);
                y[(((size_t)n * CoutTot + oca) * yH + oh) * yW + ow] = f * v.x;
                y[(((size_t)n * CoutTot + oca + 1) * yH + oh) * yW + ow] = f * v.y;
            }
            __syncthreads();
        }
    }
}

// ---------------- standalone squash (z1 > tile) ----------------
__global__ void k_squash(const float* __restrict__ x, float* __restrict__ y,
                         int N, int t1, int z1, int H, int W, int CoutTot, int ch0)
{
    int idx = blockIdx.x * blockDim.x + threadIdx.x;
    int total = N * t1 * H * W;
    if (idx >= total) return;
    int w = idx % W; int t = idx / W;
    int h = t % H;   t /= H;
    int tt = t % t1; int n = t / t1;

    size_t HW = (size_t)H * W;
    const float* xp = x + ((size_t)(n * t1 + tt) * z1) * HW + (size_t)h * W + w;
    float s2 = 0.f;
    for (int c = 0; c < z1; ++c) { float v = xp[c * HW]; s2 += v * v; }
    float f = route_f(h, w, H, W, (float)t1, s2);
    float* yp = y + ((size_t)n * CoutTot + ch0 + tt * z1) * HW + (size_t)h * W + w;
    for (int c = 0; c < z1; ++c) yp[c * HW] = f * xp[c * HW];
}

// ---------------- host dispatch ----------------
template<int KH, int KW, int S, int TOC, int Z1, bool FINAL>
static void launch_conv(const float* x, const float* w, float* y,
                        int N, int Cin, int Hin, int Win, int CinTot, int cin0,
                        int Cout, int Hout, int Wout, int padh, int padw,
                        int CoutTot, int oc0, int t1)
{
    constexpr int NC = (S == 2) ? 2 : 4;
    int nOcT = (Cout + TOC - 1) / TOC;
    dim3 grid((Wout + 31) / 32, (Hout + 7) / 8, N * nOcT);
    conv_tiled<KH, KW, S, TOC, NC, Z1, FINAL><<<grid, 256>>>(
        x, w, y, Cin, Hin, Win, CinTot, cin0,
        Cout, Hout, Wout, padh, padw, CoutTot, oc0, t1, nOcT);
}

template<int Z1>
static void launch_deconv(const float* x, const float* w, const float* b, float* y,
                          int N, int Cin, int H, int W, int Cout, int CoutTot, int t1)
{
    constexpr int TOC = 16;
    int nOcT = Cout / TOC;
    dim3 grid(W / 32, H / 8, N * nOcT);
    deconv_tiled<TOC, Z1, 2><<<grid, 256>>>(x, w, b, y, Cin, H, W, Cout, CoutTot, t1, nOcT);
}

static float* sym(const void* s)
{
    void* p = nullptr;
    cudaGetSymbolAddress(&p, (const void*)s);
    return (float*)p;
}

extern "C" void kernel_launch(void* const* d_in, const int* in_sizes, int n_in,
                              void* d_out, int out_size)
{
    const float* x    = (const float*)d_in[0];
    const float* w0   = (const float*)d_in[1];
    const float* w1a  = (const float*)d_in[2];
    const float* w1b  = (const float*)d_in[3];
    const float* w2a  = (const float*)d_in[4];
    const float* w2b  = (const float*)d_in[5];
    const float* w3a  = (const float*)d_in[6];
    const float* w3b  = (const float*)d_in[7];
    const float* w4   = (const float*)d_in[8];
    const float* b4   = (const float*)d_in[9];
    const float* w5   = (const float*)d_in[10];
    const float* w6   = (const float*)d_in[11];
    const float* b6   = (const float*)d_in[12];
    const float* w7   = (const float*)d_in[13];
    const float* w8   = (const float*)d_in[14];
    const float* b8   = (const float*)d_in[15];
    const float* w10  = (const float*)d_in[16];
    float* out = (float*)d_out;
    (void)n_in; (void)out_size;

    const int N = in_sizes[0] / (3 * 256 * 256);

    float* tmp   = sym(&g_tmp);
    float* buf1  = sym(&g_buf1);
    float* buf3  = sym(&g_buf3);
    float* buf5  = sym(&g_buf5);
    float* buf6  = sym(&g_buf6);
    float* buf9  = sym(&g_buf9);
    float* buf12 = sym(&g_buf12);
    float* cat1  = sym(&g_cat1);
    float* cat2  = sym(&g_cat2);
    float* cat3  = sym(&g_cat3);
    float* wc0   = sym(&g_wc0);
    float* wc1a  = sym(&g_wc1a);
    float* wc1b  = sym(&g_wc1b);
    float* wc2a  = sym(&g_wc2a);
    float* wc2b  = sym(&g_wc2b);
    float* wc3a  = sym(&g_wc3a);
    float* wc3b  = sym(&g_wc3b);
    float* wc5   = sym(&g_wc5);
    float* wc7   = sym(&g_wc7);
    float* wc10  = sym(&g_wc10);
    float* wdf4  = sym(&g_wdf4);
    float* wdf6  = sym(&g_wdf6);
    float* wdf8  = sym(&g_wdf8);
    float* b4s   = sym(&g_b4s);
    float* b6s   = sym(&g_b6s);
    float* b8s   = sym(&g_b8s);

    // ---- weight prep: 2 fused launches ----
    {
        PrepC pc;
        const float* srcs[10] = {w0, w1a, w1b, w2a, w2b, w3a, w3b, w5, w7, w10};
        float*       dsts[10] = {wc0, wc1a, wc1b, wc2a, wc2b, wc3a, wc3b, wc5, wc7, wc10};
        int t0s[10]   = {1, 1, 2, 4, 4, 8, 8, 16, 8, 3};
        int couts[10] = {16, 32, 64, 128, 256, 512, 256, 128, 64, 16};
        int z0s[10]   = {3, 16, 16, 16, 32, 32, 64, 32, 16, 16};
        int maxTot = 0;
        for (int i = 0; i < 10; ++i) {
            pc.src[i] = srcs[i]; pc.dst[i] = dsts[i];
            pc.t0[i] = t0s[i]; pc.Cout[i] = couts[i]; pc.z0[i] = z0s[i];
            int tot = t0s[i] * couts[i] * z0s[i] * 25;
            if (tot > maxTot) maxTot = tot;
        }
        dim3 g((maxTot + 255) / 256, 10);
        k_prep_conv<<<g, 256>>>(pc);
    }
    {
        PrepD pd;
        const float* wsrc[3] = {w4, w6, w8};
        float*       wdst[3] = {wdf4, wdf6, wdf8};
        int cins[3]  = {256, 128, 64};
        int couts[3] = {256, 64, 32};
        int t0s[3]   = {8, 4, 4};
        const float* bsrc[3] = {b4, b6, b8};
        float*       bdst[3] = {b4s, b6s, b8s};
        int maxTot = 0;
        for (int d = 0; d < 3; ++d) {
            pd.src[d] = wsrc[d]; pd.dst[d] = wdst[d];
            pd.Cin[d] = cins[d]; pd.Cout[d] = couts[d]; pd.t0[d] = t0s[d]; pd.kind[d] = 0;
            int tot = cins[d] * 25 * couts[d];
            if (tot > maxTot) maxTot = tot;
            pd.src[3 + d] = bsrc[d]; pd.dst[3 + d] = bdst[d];
            pd.Cin[3 + d] = 0; pd.Cout[3 + d] = couts[d]; pd.t0[3 + d] = t0s[d]; pd.kind[3 + d] = 1;
        }
        dim3 g((maxTot + 255) / 256, 6);
        k_prep_dec<<<g, 256>>>(pd);
    }

    // ---- forward pass ----
    // conv1 -> cat1 [32..48)  (skip1, raw)
    launch_conv<5,5,1,16,0,false>(x, wc0, cat1, N, 3,256,256, 3,0, 16,256,256, 2,2, 48,32, 0);
    // caps1a (s=2, t1=2 z1=16) fused squash -> buf1
    launch_conv<5,5,2,32,16,false>(cat1, wc1a, buf1, N, 16,256,256, 48,32, 32,128,128, 2,2, 32,0, 2);
    // caps1b (t1=4 z1=16) fused -> cat2 [64..128) (skip2)
    launch_conv<5,5,1,32,16,false>(buf1, wc1b, cat2, N, 32,128,128, 32,0, 64,128,128, 2,2, 128,64, 4);
    // caps2a (s=2, t1=4 z1=32) fused -> buf3
    launch_conv<5,5,2,32,32,false>(cat2, wc2a, buf3, N, 64,128,128, 128,64, 128,64,64, 2,2, 128,0, 4);
    // caps2b (t1=8 z1=32) fused -> cat3 [256..512) (skip3)
    launch_conv<5,5,1,32,32,false>(buf3, wc2b, cat3, N, 128,64,64, 128,0, 256,64,64, 2,2, 512,256, 8);
    // caps3a (s=2, t1=8 z1=64): z1 > tile -> unfused
    launch_conv<5,5,2,16,0,false>(cat3, wc3a, tmp, N, 256,64,64, 512,256, 512,32,32, 2,2, 512,0, 0);
    k_squash<<<(N*8*32*32 + 255)/256, 256>>>(tmp, buf5, N, 8,64,32,32, 512,0);
    // caps3b (t1=8 z1=32): TOC=16 < z1 -> unfused
    launch_conv<5,5,1,16,0,false>(buf5, wc3b, tmp, N, 512,32,32, 512,0, 256,32,32, 2,2, 256,0, 0);
    k_squash<<<(N*8*32*32 + 255)/256, 256>>>(tmp, buf6, N, 8,32,32,32, 256,0);
    // deconv w4 (t1=8 z1=32): fused 4-parity, squash separate
    launch_deconv<0>(buf6, wdf4, b4s, tmp, N, 256, 32, 32, 256, 256, 0);
    k_squash<<<(N*8*64*64 + 255)/256, 256>>>(tmp, cat3, N, 8,32,64,64, 512,0);
    // caps w5 (t1=4 z1=32) fused -> buf9
    launch_conv<5,5,1,32,32,false>(cat3, wc5, buf9, N, 512,64,64, 512,0, 128,64,64, 2,2, 128,0, 4);
    // deconv w6 (t1=4 z1=16): fused parity + squash -> cat2 [0..64)
    launch_deconv<16>(buf9, wdf6, b6s, cat2, N, 128, 64, 64, 64, 128, 4);
    // caps w7 (t1=4 z1=16) fused -> buf12
    launch_conv<5,5,1,32,16,false>(cat2, wc7, buf12, N, 128,128,128, 128,0, 64,128,128, 2,2, 64,0, 4);
    // deconv w8 (t1=2 z1=16): fused parity + squash -> cat1 [0..32)
    launch_deconv<16>(buf12, wdf8, b8s, cat1, N, 64, 128, 128, 32, 48, 2);
    // caps w10 (t1=1 z1=16) fused squash + final norm -> out
    launch_conv<5,5,1,16,16,true>(cat1, wc10, out, N, 48,256,256, 48,0, 16,256,256, 2,2, 1,0, 1);
}